// round 11
// baseline (speedup 1.0000x reference)
#include <cuda_runtime.h>
#include <cuda_bf16.h>
#include <mma.h>
#include <cstdint>
#include <math.h>

using namespace nvcuda;

// ---------------- problem constants ----------------
// B=4 S=3 E=7 IMG=256 PH=8 H=32 D=128 NH=4 DK=64 DC=128 DH=32 TEMB=256 LK=128 GROUPS=16
#define EPSV 1e-5f

// ---------------- scratch buffers (device globals; no allocation) ----------------
__device__ float g_xin [12 * 448 * 1024];   // patchified input (12,448,32,32)
__device__ float g_xg  [4 * 393216];        // conv1 out in xg flat layout (B, 393216)
__device__ float g_gn_mu[64];
__device__ float g_gn_rs[64];
__device__ float g_xq  [4096 * 128];        // S-collapsed normalized features
__device__ float g_q   [4096 * 256];        // query projections
__device__ float g_oflat[4096 * 128];       // attention output, (Nq, DC) flat
__device__ float g_o2  [4 * 128 * 1024];    // outproj output as (4,128,32,32)
__device__ float g_u   [4 * 7 * 65536];     // unpatched image (B,E,256,256) == skip
__device__ float g_mod [4 * 14];
__device__ float g_lnp [4 * 32 * 2];
__device__ float g_ln  [4 * 2];             // per-batch mu, rstd

// tap-major weights for implicit conv: Bt[tap][oc][hi(IC)|lo(IC)] bf16
__device__ __align__(16) __nv_bfloat16 g_Bt1[9ull * 128 * 2 * 448];  // 2 MB
__device__ __align__(16) __nv_bfloat16 g_Bt2[9ull * 448 * 2 * 128];  // 2 MB
// conv1 K-split partial sums: 7 x [12288 px][128 oc] f32
__device__ float g_p1[7ull * 1572864];

// ---------------- helpers ----------------
__device__ __forceinline__ uint32_t smem_u32(const void* p) {
    return (uint32_t)__cvta_generic_to_shared(p);
}
__device__ __forceinline__ void cp16(uint32_t dst, const void* src) {
    asm volatile("cp.async.ca.shared.global [%0], [%1], 16;" :: "r"(dst), "l"(src));
}
__device__ __forceinline__ void cp_commit() {
    asm volatile("cp.async.commit_group;" ::: "memory");
}
__device__ __forceinline__ void cp_wait_all() {
    asm volatile("cp.async.wait_group 0;" ::: "memory");
}

// ---------------- K1: patchify (smem transpose, both sides coalesced) ----------------
__global__ void __launch_bounds__(256) k_patchify(const float* __restrict__ x) {
    __shared__ float s[1024];
    int blk    = blockIdx.x;        // 12*7*64
    int rowblk = blk & 63;          // group of 4 input rows
    int ime    = blk >> 6;          // img*7 + e
    int img = ime / 7, e = ime % 7;
    int t = threadIdx.x;
    const float* src = x + ((size_t)ime * 256 + rowblk * 4) * 256;
    s[t]       = src[t];
    s[t + 256] = src[t + 256];
    s[t + 512] = src[t + 512];
    s[t + 768] = src[t + 768];
    __syncthreads();
    int ph2 = t >> 5, xx = t & 31;
#pragma unroll
    for (int r = 0; r < 4; ++r) {
        int Y = rowblk * 4 + r;
        int ph1 = Y & 7, y = Y >> 3;
        int ic = ph1 * 56 + ph2 * 7 + e;
        g_xin[((img * 448 + ic) << 10) + (y << 5) + xx] = s[r * 256 + xx * 8 + ph2];
    }
}

// ---------------- weight prep: w[oc][ic*9+tap] fp32 -> Bt[tap][oc][hi|lo] bf16 ----------------
__global__ void k_prepT(const float* __restrict__ w, __nv_bfloat16* __restrict__ Bt,
                        int OC, int IC) {
    int idx = blockIdx.x * 256 + threadIdx.x;
    if (idx >= OC * IC * 9) return;
    int K = IC * 9;
    int oc = idx / K, k = idx - oc * K;
    int ic = k / 9, tap = k - ic * 9;
    float v = w[idx];
    __nv_bfloat16 h = __float2bfloat16(v);
    float lo = v - __bfloat162float(h);
    size_t base = (((size_t)tap * OC + oc) * 2) * IC + ic;
    Bt[base]      = h;
    Bt[base + IC] = __float2bfloat16(lo);
}

// ---------------- implicit conv via WMMA, no im2col ----------------
// Per ic-chunk (64): stage fp32 halo tile [64][6][34], transpose/convert to bf16
// hi/lo [pos][ic], 9 taps reuse it with shifted bases. B staged per tap with
// cp.async, double-buffered (prefetch next tap during current mma).
// EPI 0: conv1, K-split: blockIdx.y = chunk; partial out to pout (no bias).
// EPI 1: conv2, blockIdx.y = N-tile; full K; unpatch scatter + bias to g_u.
// smem layout (bytes):
//   [0, 53504)           s32 [64][209] f32       (epilogue overlays sD [128][132] f32)
//   [53504, 82880)       sAh [204][72] bf16
//   [82880, 112256)      sAl [204][72] bf16
//   [112256, 185984)     sB: 2 bufs x (hi 18432 + lo 18432)
template<int IC, int EPI>
__global__ void __launch_bounds__(512) k_conv(const float* __restrict__ Xg,
                                              const __nv_bfloat16* __restrict__ Bt,
                                              const float* __restrict__ bias,
                                              float* __restrict__ pout) {
    extern __shared__ __align__(16) char smem[];
    const int OC   = (EPI == 0) ? 128 : 448;
    const int S32L = 209;
    const int LDA  = 72;
    float* s32         = (float*)smem;
    __nv_bfloat16* sAh = (__nv_bfloat16*)(smem + 53504);
    __nv_bfloat16* sAl = (__nv_bfloat16*)(smem + 82880);
    float* sD          = (float*)smem;
    const uint32_t bB  = smem_u32(smem) + 112256u;   // B buffers base

    int t = threadIdx.x;
    int w = t >> 5;
    int wm = w >> 2, wn = w & 3;
    int bx = blockIdx.x;
    int img = bx >> 3, rb = bx & 7;
    int y0 = rb * 4;
    int m0 = bx * 128;
    int n0     = (EPI == 0) ? 0 : (int)blockIdx.y * 128;
    int cstart = (EPI == 0) ? (int)blockIdx.y : 0;
    int cend   = (EPI == 0) ? cstart + 1 : IC / 64;
    int nch    = cend - cstart;
    int total_taps = nch * 9;

    // pre-zero invalid B rows (conv2 last N-tile); never overwritten by cp.async
    if (n0 + 127 >= OC) {
        for (int idx = t; idx < 4096; idx += 512) {
            int seg = idx & 7;
            int row = (idx >> 3) & 127;
            int sel = (idx >> 10) & 1;
            int b2  = idx >> 11;
            if (n0 + row >= OC) {
                uint4 z; z.x = 0u; z.y = 0u; z.z = 0u; z.w = 0u;
                *(uint4*)(smem + 112256 + b2 * 36864 + sel * 18432
                          + (row * LDA + seg * 8) * 2) = z;
            }
        }
    }

    wmma::fragment<wmma::accumulator, 16, 16, 16, float> acc[2][2];
#pragma unroll
    for (int i = 0; i < 2; ++i)
#pragma unroll
        for (int j = 0; j < 2; ++j) wmma::fill_fragment(acc[i][j], 0.f);

    // stage B(tap) for chunk ch into buffer bsel via cp.async (16B granules)
    auto stageB = [&](int ch, int tap, int bsel) {
#pragma unroll
        for (int i = 0; i < 4; ++i) {
            int idx = t + i * 512;
            int seg = idx & 7;
            int row = (idx >> 3) & 127;
            int sel = idx >> 10;
            int oc  = n0 + row;
            if (oc < OC) {
                const __nv_bfloat16* src =
                    Bt + (((size_t)tap * OC + oc) * 2 + sel) * IC + ch * 64 + seg * 8;
                cp16(bB + (uint32_t)(bsel * 36864 + sel * 18432 + (row * LDA + seg * 8) * 2),
                     src);
            }
        }
    };

    // prologue prefetch: first tap of first chunk into buf 0
    stageB(cstart, 0, 0);
    cp_commit();
    int buf = 0;

    for (int gc = 0; gc < nch; ++gc) {
        int ch = cstart + gc;
        // ---- stage fp32 halo tile ----
        for (int idx = t; idx < 64 * 204; idx += 512) {
            int c  = idx / 204;
            int rr = idx - c * 204;
            int ry = rr / 34, cx = rr - ry * 34;
            int y = y0 - 1 + ry;
            int x = cx - 1;
            float v = 0.f;
            if (y >= 0 && y < 32 && x >= 0 && x < 32)
                v = Xg[((size_t)(img * IC + ch * 64 + c) << 10) + (y << 5) + x];
            s32[c * S32L + rr] = v;
        }
        __syncthreads();   // also guarantees prev chunk's mma done before sA rewrite
        // ---- transpose + hi/lo convert ----
        for (int idx = t; idx < 8 * 204; idx += 512) {
            int icg = idx / 204;
            int p   = idx - icg * 204;
            uint4 vh, vl;
            uint32_t hw[4], lw[4];
#pragma unroll
            for (int pr = 0; pr < 4; ++pr) {
                float v0 = s32[(icg * 8 + pr * 2 + 0) * S32L + p];
                float v1 = s32[(icg * 8 + pr * 2 + 1) * S32L + p];
                __nv_bfloat16 h0 = __float2bfloat16(v0);
                __nv_bfloat16 h1 = __float2bfloat16(v1);
                __nv_bfloat16 l0 = __float2bfloat16(v0 - __bfloat162float(h0));
                __nv_bfloat16 l1 = __float2bfloat16(v1 - __bfloat162float(h1));
                hw[pr] = (uint32_t)__bfloat16_as_ushort(h0)
                       | ((uint32_t)__bfloat16_as_ushort(h1) << 16);
                lw[pr] = (uint32_t)__bfloat16_as_ushort(l0)
                       | ((uint32_t)__bfloat16_as_ushort(l1) << 16);
            }
            vh.x = hw[0]; vh.y = hw[1]; vh.z = hw[2]; vh.w = hw[3];
            vl.x = lw[0]; vl.y = lw[1]; vl.z = lw[2]; vl.w = lw[3];
            *(uint4*)&sAh[p * LDA + icg * 8] = vh;
            *(uint4*)&sAl[p * LDA + icg * 8] = vl;
        }
        __syncthreads();
        // ---- 9 taps, B double-buffered ----
        for (int tap = 0; tap < 9; ++tap) {
            cp_wait_all();
            __syncthreads();
            int g = gc * 9 + tap;
            if (g + 1 < total_taps) {
                int gn = g + 1;
                stageB(cstart + gn / 9, gn - (gn / 9) * 9, buf ^ 1);
            }
            cp_commit();
            __nv_bfloat16* sBh = (__nv_bfloat16*)(smem + 112256 + buf * 36864);
            __nv_bfloat16* sBl = sBh + 9216;   // 18432 B
            int dy = tap / 3 - 1, dx = tap - (tap / 3) * 3 - 1;
            int abase = ((1 + dy + wm) * 34 + (1 + dx)) * LDA;
#pragma unroll
            for (int ks = 0; ks < 4; ++ks) {
                int kk = ks * 16;
                wmma::fragment<wmma::matrix_a, 16, 16, 16, __nv_bfloat16, wmma::row_major> ah[2], al[2];
                wmma::fragment<wmma::matrix_b, 16, 16, 16, __nv_bfloat16, wmma::col_major> bh[2], bl[2];
                wmma::load_matrix_sync(ah[0], sAh + abase + 0  * LDA + kk, LDA);
                wmma::load_matrix_sync(ah[1], sAh + abase + 16 * LDA + kk, LDA);
                wmma::load_matrix_sync(al[0], sAl + abase + 0  * LDA + kk, LDA);
                wmma::load_matrix_sync(al[1], sAl + abase + 16 * LDA + kk, LDA);
                wmma::load_matrix_sync(bh[0], sBh + (wn * 32 + 0)  * LDA + kk, LDA);
                wmma::load_matrix_sync(bh[1], sBh + (wn * 32 + 16) * LDA + kk, LDA);
                wmma::load_matrix_sync(bl[0], sBl + (wn * 32 + 0)  * LDA + kk, LDA);
                wmma::load_matrix_sync(bl[1], sBl + (wn * 32 + 16) * LDA + kk, LDA);
#pragma unroll
                for (int i = 0; i < 2; ++i)
#pragma unroll
                    for (int j = 0; j < 2; ++j) {
                        wmma::mma_sync(acc[i][j], ah[i], bh[j], acc[i][j]);
                        wmma::mma_sync(acc[i][j], ah[i], bl[j], acc[i][j]);
                        wmma::mma_sync(acc[i][j], al[i], bh[j], acc[i][j]);
                    }
            }
            __syncthreads();
            buf ^= 1;
        }
    }

    // ---- epilogue ----
#pragma unroll
    for (int i = 0; i < 2; ++i)
#pragma unroll
        for (int j = 0; j < 2; ++j)
            wmma::store_matrix_sync(sD + (wm * 32 + i * 16) * 132 + wn * 32 + j * 16,
                                    acc[i][j], 132, wmma::mem_row_major);
    __syncthreads();

    int r = t & 127, q = t >> 7;
    int px = m0 + r;
    const float* drow = sD + r * 132 + q * 32;
    if (EPI == 0) {
        // partial: [px][oc] flat, coalesced 32-contig per thread
        float* dst = pout + (size_t)blockIdx.y * 1572864 + (size_t)px * 128 + q * 32;
#pragma unroll
        for (int c = 0; c < 32; ++c) dst[c] = drow[c];
    } else {
        int im = px >> 10, p = px & 1023;
        int y = p >> 5, xg = p & 31;
#pragma unroll
        for (int c = 0; c < 32; ++c) {
            int oc = n0 + q * 32 + c;
            if (oc < 448) {
                int p1 = oc / 56, rr2 = oc - p1 * 56;
                int p2 = rr2 / 7, e = rr2 - p2 * 7;
                g_u[((size_t)(im * 7 + e) * 256 + (size_t)(y * 8 + p1)) * 256
                    + (size_t)(xg * 8 + p2)] = drow[c] + bias[oc];
            }
        }
    }
}

// ---------------- combine conv1 partials: sum 7 + bias + pos -> g_xg layout ----------------
__global__ void __launch_bounds__(256) k_comb(const float* __restrict__ bias,
                                              const float* __restrict__ pos) {
    extern __shared__ float sc[];   // [128][133]
    int blk = blockIdx.x;           // 96: px tile of 128
    int t = threadIdx.x;
    size_t f0 = (size_t)blk * 16384;
    for (int idx = t; idx < 16384; idx += 256) {
        float s = 0.f;
#pragma unroll
        for (int k = 0; k < 7; ++k) s += g_p1[(size_t)k * 1572864 + f0 + idx];
        sc[(idx >> 7) * 133 + (idx & 127)] = s;
    }
    __syncthreads();
    int px0 = blk * 128;
    int img = px0 >> 10, p0 = px0 & 1023;
    int b = img / 3, ss = img - b * 3;
    float* dst = g_xg + b * 393216 + ss * 131072;
    for (int idx = t; idx < 16384; idx += 256) {
        int oc = idx >> 7, i = idx & 127;
        dst[oc * 1024 + p0 + i] = sc[i * 133 + oc] + bias[oc] + pos[oc * 1024 + p0 + i];
    }
}

// ---------------- K3: GroupNorm stats (64 contiguous groups of 24576) ----------------
__global__ void k_gnstats() {
    int bg = blockIdx.x;
    const float* p = g_xg + bg * 24576;
    int t = threadIdx.x;
    float s = 0.f, s2 = 0.f;
    for (int i = t; i < 24576; i += 256) { float v = p[i]; s += v; s2 += v * v; }
    __shared__ float rs[256], rq[256];
    rs[t] = s; rq[t] = s2; __syncthreads();
    for (int off = 128; off > 0; off >>= 1) {
        if (t < off) { rs[t] += rs[t + off]; rq[t] += rq[t + off]; }
        __syncthreads();
    }
    if (t == 0) {
        float mu = rs[0] * (1.f / 24576.f);
        float var = rq[0] * (1.f / 24576.f) - mu * mu;
        g_gn_mu[bg] = mu;
        g_gn_rs[bg] = rsqrtf(var + EPSV);
    }
}

// ---------------- K4: S-collapse with GN applied ----------------
__global__ void k_xq(const float* __restrict__ gamma, const float* __restrict__ beta,
                     const float* __restrict__ w2) {
    int idx = blockIdx.x * 256 + threadIdx.x;
    if (idx >= 4096 * 128) return;
    int nq = idx >> 7, dq = idx & 127;
    int b = nq >> 10;
    int fbase = (nq & 1023) * 384 + dq * 3;
    const float* xb = g_xg + b * 393216;
    float accv = 0.f;
#pragma unroll
    for (int sq = 0; sq < 3; ++sq) {
        int f  = fbase + sq;
        int dp = f / 3072;
        int gi = b * 16 + f / 24576;
        float v = xb[f];
        float xn = (v - g_gn_mu[gi]) * g_gn_rs[gi] * gamma[dp] + beta[dp];
        accv = fmaf(w2[sq], xn, accv);
    }
    g_xq[idx] = accv;
}

// ---------------- K5: q GEMM (4096x128 @ 128x256) ----------------
__global__ void __launch_bounds__(256) k_qgemm(const float* __restrict__ w1,
                                               const float* __restrict__ b1,
                                               const float* __restrict__ w2,
                                               const float* __restrict__ b2p) {
    __shared__ float As[64 * 68];
    __shared__ float Bs[64 * 68];
    int r0 = blockIdx.x * 64, o0 = blockIdx.y * 64;
    int t = threadIdx.x;
    int cth = (t & 15) * 4, rth = (t >> 4) * 4;
    float acc[4][4];
#pragma unroll
    for (int a = 0; a < 4; ++a)
#pragma unroll
        for (int c = 0; c < 4; ++c) acc[a][c] = 0.f;

    for (int k0 = 0; k0 < 128; k0 += 64) {
        __syncthreads();
        for (int idx = t; idx < 4096; idx += 256) {
            int jj = idx & 63, rr = idx >> 6;
            As[jj * 68 + rr] = g_xq[(r0 + rr) * 128 + k0 + jj];
            Bs[jj * 68 + rr] = w1[(o0 + rr) * 128 + k0 + jj];
        }
        __syncthreads();
#pragma unroll 8
        for (int j = 0; j < 64; ++j) {
            float4 av = *(const float4*)&As[j * 68 + rth];
            float4 bv = *(const float4*)&Bs[j * 68 + cth];
            float a[4] = {av.x, av.y, av.z, av.w};
            float bb[4] = {bv.x, bv.y, bv.z, bv.w};
#pragma unroll
            for (int r = 0; r < 4; ++r)
#pragma unroll
                for (int c = 0; c < 4; ++c) acc[r][c] = fmaf(a[r], bb[c], acc[r][c]);
        }
    }
    float w2s = w2[0] + w2[1] + w2[2];
    float b2v = b2p[0];
#pragma unroll
    for (int r = 0; r < 4; ++r)
#pragma unroll
        for (int c = 0; c < 4; ++c) {
            int o = o0 + cth + c;
            g_q[(r0 + rth + r) * 256 + o] = acc[r][c] + b1[o] * w2s + b2v;
        }
}

// ---------------- K6: per-row attention (16384 rows) ----------------
__global__ void __launch_bounds__(128) k_attn(const float* __restrict__ kc,
                                              const float* __restrict__ vc) {
    int n = blockIdx.x;
    int t = threadIdx.x;
    int lane = t & 31, wid = t >> 5;
    __shared__ float attn_s[128];
    __shared__ float red[128];

    const float* qp = g_q + (size_t)(n >> 2) * 256 + (n & 3) * 64;
    float2 q2 = *(const float2*)(qp + 2 * lane);
    const float* kb = kc + (size_t)n * 8192;

#pragma unroll 4
    for (int i = 0; i < 32; ++i) {
        int l = wid * 32 + i;
        float2 kv = *(const float2*)(kb + l * 64 + 2 * lane);
        float p = q2.x * kv.x + q2.y * kv.y;
        p += __shfl_xor_sync(0xffffffffu, p, 16);
        p += __shfl_xor_sync(0xffffffffu, p, 8);
        p += __shfl_xor_sync(0xffffffffu, p, 4);
        p += __shfl_xor_sync(0xffffffffu, p, 2);
        p += __shfl_xor_sync(0xffffffffu, p, 1);
        if (lane == i) attn_s[l] = p * 0.125f;
    }
    __syncthreads();

    float v = attn_s[t];
    float m = v;
    m = fmaxf(m, __shfl_xor_sync(0xffffffffu, m, 16));
    m = fmaxf(m, __shfl_xor_sync(0xffffffffu, m, 8));
    m = fmaxf(m, __shfl_xor_sync(0xffffffffu, m, 4));
    m = fmaxf(m, __shfl_xor_sync(0xffffffffu, m, 2));
    m = fmaxf(m, __shfl_xor_sync(0xffffffffu, m, 1));
    if (lane == 0) red[wid] = m;
    __syncthreads();
    float bm = fmaxf(fmaxf(red[0], red[1]), fmaxf(red[2], red[3]));
    float e = expf(v - bm);
    float s = e;
    s += __shfl_xor_sync(0xffffffffu, s, 16);
    s += __shfl_xor_sync(0xffffffffu, s, 8);
    s += __shfl_xor_sync(0xffffffffu, s, 4);
    s += __shfl_xor_sync(0xffffffffu, s, 2);
    s += __shfl_xor_sync(0xffffffffu, s, 1);
    __syncthreads();
    if (lane == 0) red[wid] = s;
    __syncthreads();
    float bs = red[0] + red[1] + red[2] + red[3];
    attn_s[t] = e * (1.f / bs);
    __syncthreads();

    int c = t & 31, chunk = t >> 5;
    const float* vb = vc + (size_t)n * 4096;
    float acc = 0.f;
#pragma unroll 8
    for (int i = 0; i < 32; ++i) {
        int l = chunk * 32 + i;
        acc = fmaf(attn_s[l], vb[l * 32 + c], acc);
    }
    __syncthreads();
    red[t] = acc;
    __syncthreads();
    if (t < 32) {
        float o = red[t] + red[32 + t] + red[64 + t] + red[96 + t];
        g_oflat[(n & 4095) * 128 + (n >> 12) * 32 + t] = o;
    }
}

// ---------------- K7: outproj 128x128 per-pixel matvec ----------------
__global__ void __launch_bounds__(256) k_outproj(const float* __restrict__ w,
                                                 const float* __restrict__ bias) {
    __shared__ float in_s[32 * 128];
    __shared__ float w_s[32 * 36];
    int b = blockIdx.x >> 3, pt = blockIdx.x & 7;
    int oc0 = blockIdx.y * 32;
    int t = threadIdx.x;
    int tx = t & 15, ty = t >> 4;
    int p0 = tx * 8, ol = ty * 2;
    float acc[2][8];
#pragma unroll
    for (int j = 0; j < 2; ++j)
#pragma unroll
        for (int i = 0; i < 8; ++i) acc[j][i] = 0.f;

    for (int c0 = 0; c0 < 128; c0 += 32) {
        __syncthreads();
        for (int idx = t; idx < 32 * 128; idx += 256) {
            int c = idx >> 7, p = idx & 127;
            in_s[idx] = g_oflat[b * 131072 + (c0 + c) * 1024 + pt * 128 + p];
        }
        for (int idx = t; idx < 32 * 32; idx += 256) {
            int c = idx & 31, o = idx >> 5;
            w_s[c * 36 + o] = w[(oc0 + o) * 128 + c0 + c];
        }
        __syncthreads();
#pragma unroll 4
        for (int c = 0; c < 32; ++c) {
            float w0 = w_s[c * 36 + ol], w1 = w_s[c * 36 + ol + 1];
            float4 i0 = *(const float4*)&in_s[c * 128 + p0];
            float4 i1 = *(const float4*)&in_s[c * 128 + p0 + 4];
            float iv[8] = {i0.x, i0.y, i0.z, i0.w, i1.x, i1.y, i1.z, i1.w};
#pragma unroll
            for (int i = 0; i < 8; ++i) {
                acc[0][i] = fmaf(w0, iv[i], acc[0][i]);
                acc[1][i] = fmaf(w1, iv[i], acc[1][i]);
            }
        }
    }
#pragma unroll
    for (int j = 0; j < 2; ++j) {
        int oc = oc0 + ol + j;
        float bv = bias[oc];
#pragma unroll
        for (int i = 0; i < 8; ++i)
            g_o2[(b * 128 + oc) * 1024 + pt * 128 + p0 + i] = acc[j][i] + bv;
    }
}

// ---------------- K9: modulation ----------------
__global__ void k_mod(const float* __restrict__ emb, const float* __restrict__ mw,
                      const float* __restrict__ mb) {
    int t = threadIdx.x;
    if (t < 56) {
        int b = t / 14, o = t % 14;
        float accv = mb[o];
        for (int k = 0; k < 256; ++k) {
            float e = emb[b * 256 + k];
            float si = e / (1.f + expf(-e));
            accv = fmaf(si, mw[o * 256 + k], accv);
        }
        g_mod[t] = accv;
    }
}

// ---------------- K10/K11: LayerNorm over u per batch ----------------
__global__ void k_lnpart() {
    int bidx = blockIdx.x;
    int b = bidx >> 5, part = bidx & 31;
    const float* p = g_u + b * 458752 + part * 14336;
    int t = threadIdx.x;
    float s = 0.f, s2 = 0.f;
    for (int i = t; i < 14336; i += 256) { float v = p[i]; s += v; s2 += v * v; }
    __shared__ float rs[256], rq[256];
    rs[t] = s; rq[t] = s2; __syncthreads();
    for (int off = 128; off > 0; off >>= 1) {
        if (t < off) { rs[t] += rs[t + off]; rq[t] += rq[t + off]; }
        __syncthreads();
    }
    if (t == 0) { g_lnp[bidx * 2] = rs[0]; g_lnp[bidx * 2 + 1] = rq[0]; }
}

__global__ void k_lnfin() {
    int t = threadIdx.x;
    if (t < 4) {
        float s = 0.f, s2 = 0.f;
        for (int i = 0; i < 32; ++i) {
            s  += g_lnp[(t * 32 + i) * 2];
            s2 += g_lnp[(t * 32 + i) * 2 + 1];
        }
        float mu = s * (1.f / 458752.f);
        float var = s2 * (1.f / 458752.f) - mu * mu;
        g_ln[t * 2] = mu;
        g_ln[t * 2 + 1] = rsqrtf(var + EPSV);
    }
}

// ---------------- K12: final elementwise tail ----------------
__device__ __forceinline__ float gelu_exact(float x) {
    return 0.5f * x * (1.f + erff(x * 0.70710678118654752f));
}

__global__ void k_final(const float* __restrict__ ew, const float* __restrict__ eb,
                        const float* __restrict__ fw, const float* __restrict__ fb,
                        float* __restrict__ out) {
    int gid = blockIdx.x * 256 + threadIdx.x;
    if (gid >= 262144) return;
    int b = gid >> 16, p = gid & 65535;
    float mu = g_ln[b * 2], rsd = g_ln[b * 2 + 1];
    float uv[7], un[7];
#pragma unroll
    for (int e = 0; e < 7; ++e) {
        uv[e] = g_u[b * 458752 + e * 65536 + p];
        float sc = g_mod[b * 14 + e];
        float sh = g_mod[b * 14 + 7 + e];
        un[e] = (uv[e] - mu) * rsd * (1.f + sc) + sh;
    }
    float en[14];
#pragma unroll
    for (int o = 0; o < 14; ++o) {
        float a = eb[o];
#pragma unroll
        for (int e = 0; e < 7; ++e) a = fmaf(ew[o * 7 + e], un[e], a);
        en[o] = a;
    }
    float hf[7];
#pragma unroll
    for (int e = 0; e < 7; ++e)
        hf[e] = gelu_exact(un[e]) + en[e] * gelu_exact(en[7 + e]);
#pragma unroll
    for (int o = 0; o < 7; ++o) {
        float a = fb[o];
#pragma unroll
        for (int e = 0; e < 7; ++e) a = fmaf(fw[o * 7 + e], hf[e], a);
        out[b * 458752 + o * 65536 + p] = a + uv[o];
    }
}

// ---------------- launch ----------------
extern "C" void kernel_launch(void* const* d_in, const int* in_sizes, int n_in,
                              void* d_out, int out_size) {
    const float* x    = (const float*)d_in[0];
    const float* kc   = (const float*)d_in[1];
    const float* vc   = (const float*)d_in[2];
    const float* emb  = (const float*)d_in[3];
    const float* pos  = (const float*)d_in[4];
    const float* pw   = (const float*)d_in[5];
    const float* pb   = (const float*)d_in[6];
    const float* gg   = (const float*)d_in[7];
    const float* gb   = (const float*)d_in[8];
    const float* w1   = (const float*)d_in[9];
    const float* b1   = (const float*)d_in[10];
    const float* w2   = (const float*)d_in[11];
    const float* b2   = (const float*)d_in[12];
    const float* ow   = (const float*)d_in[13];
    const float* ob   = (const float*)d_in[14];
    const float* uw   = (const float*)d_in[15];
    const float* ub   = (const float*)d_in[16];
    const float* mw   = (const float*)d_in[17];
    const float* mb   = (const float*)d_in[18];
    const float* ew   = (const float*)d_in[19];
    const float* ebb  = (const float*)d_in[20];
    const float* fw   = (const float*)d_in[21];
    const float* fb   = (const float*)d_in[22];
    float* out = (float*)d_out;

    const int DSMEM = 185984;
    const int CSMEM = 128 * 133 * 4;   // 68096
    cudaFuncSetAttribute(k_conv<448, 0>,
                         cudaFuncAttributeMaxDynamicSharedMemorySize, DSMEM);
    cudaFuncSetAttribute(k_conv<128, 1>,
                         cudaFuncAttributeMaxDynamicSharedMemorySize, DSMEM);
    cudaFuncSetAttribute(k_comb,
                         cudaFuncAttributeMaxDynamicSharedMemorySize, CSMEM);

    __nv_bfloat16 *pBt1, *pBt2;
    cudaGetSymbolAddress((void**)&pBt1, g_Bt1);
    cudaGetSymbolAddress((void**)&pBt2, g_Bt2);
    float* pXin; cudaGetSymbolAddress((void**)&pXin, g_xin);
    float* pO2;  cudaGetSymbolAddress((void**)&pO2,  g_o2);
    float* pP1;  cudaGetSymbolAddress((void**)&pP1,  g_p1);

    k_patchify<<<5376, 256>>>(x);
    k_prepT<<<(128 * 448 * 9 + 255) / 256, 256>>>(pw, pBt1, 128, 448);
    k_prepT<<<(448 * 128 * 9 + 255) / 256, 256>>>(uw, pBt2, 448, 128);
    k_conv<448, 0><<<dim3(96, 7), 512, DSMEM>>>(pXin, pBt1, (const float*)0, pP1);
    k_comb<<<96, 256, CSMEM>>>(pb, pos);
    k_gnstats<<<64, 256>>>();
    k_xq<<<2048, 256>>>(gg, gb, w2);
    k_qgemm<<<dim3(64, 4), 256>>>(w1, b1, w2, b2);
    k_attn<<<16384, 128>>>(kc, vc);
    k_outproj<<<dim3(32, 4), 256>>>(ow, ob);
    k_conv<128, 1><<<dim3(32, 4), 512, DSMEM>>>(pO2, pBt2, ub, (float*)0);
    k_mod<<<1, 64>>>(emb, mw, mb);
    k_lnpart<<<128, 256>>>();
    k_lnfin<<<1, 32>>>();
    k_final<<<1024, 256>>>(ew, ebb, fw, fb, out);
}

// round 13
// speedup vs baseline: 1.0504x; 1.0504x over previous
#include <cuda_runtime.h>
#include <cuda_bf16.h>
#include <mma.h>
#include <cstdint>
#include <math.h>

using namespace nvcuda;

// ---------------- problem constants ----------------
// B=4 S=3 E=7 IMG=256 PH=8 H=32 D=128 NH=4 DK=64 DC=128 DH=32 TEMB=256 LK=128 GROUPS=16
#define EPSV 1e-5f

// ---------------- scratch buffers (device globals; no allocation) ----------------
__device__ float g_xin [12 * 448 * 1024];   // patchified input (12,448,32,32)
__device__ float g_xg  [4 * 393216];        // conv1 out in xg flat layout (B, 393216)
__device__ float g_gn_mu[64];
__device__ float g_gn_rs[64];
__device__ float g_xq  [4096 * 128];        // S-collapsed normalized features
__device__ float g_q   [4096 * 256];        // query projections
__device__ float g_oflat[4096 * 128];       // attention output, (Nq, DC) flat
__device__ float g_o2  [4 * 128 * 1024];    // outproj output as (4,128,32,32)
__device__ float g_u   [4 * 7 * 65536];     // unpatched image (B,E,256,256) == skip
__device__ float g_mod [4 * 14];
__device__ float g_lnp [4 * 32 * 2];
__device__ float g_ln  [4 * 2];             // per-batch mu, rstd

// tap-major weights for implicit conv: Bt[tap][oc][hi(IC)|lo(IC)] bf16
__device__ __align__(16) __nv_bfloat16 g_Bt1[9ull * 128 * 2 * 448];  // 2 MB
__device__ __align__(16) __nv_bfloat16 g_Bt2[9ull * 448 * 2 * 128];  // 2 MB

// ---------------- helpers ----------------
__device__ __forceinline__ uint32_t smem_u32(const void* p) {
    return (uint32_t)__cvta_generic_to_shared(p);
}
__device__ __forceinline__ void cp16(uint32_t dst, const void* src) {
    asm volatile("cp.async.ca.shared.global [%0], [%1], 16;" :: "r"(dst), "l"(src));
}
__device__ __forceinline__ void cp_commit() {
    asm volatile("cp.async.commit_group;" ::: "memory");
}
__device__ __forceinline__ void cp_wait_all() {
    asm volatile("cp.async.wait_group 0;" ::: "memory");
}

// ---------------- K1: patchify (smem transpose, both sides coalesced) ----------------
__global__ void __launch_bounds__(256) k_patchify(const float* __restrict__ x) {
    __shared__ float s[1024];
    int blk    = blockIdx.x;        // 12*7*64
    int rowblk = blk & 63;          // group of 4 input rows
    int ime    = blk >> 6;          // img*7 + e
    int img = ime / 7, e = ime % 7;
    int t = threadIdx.x;
    const float* src = x + ((size_t)ime * 256 + rowblk * 4) * 256;
    s[t]       = src[t];
    s[t + 256] = src[t + 256];
    s[t + 512] = src[t + 512];
    s[t + 768] = src[t + 768];
    __syncthreads();
    int ph2 = t >> 5, xx = t & 31;
#pragma unroll
    for (int r = 0; r < 4; ++r) {
        int Y = rowblk * 4 + r;
        int ph1 = Y & 7, y = Y >> 3;
        int ic = ph1 * 56 + ph2 * 7 + e;
        g_xin[((img * 448 + ic) << 10) + (y << 5) + xx] = s[r * 256 + xx * 8 + ph2];
    }
}

// ---------------- weight prep: w[oc][ic*9+tap] fp32 -> Bt[tap][oc][hi|lo] bf16 ----------------
__global__ void k_prepT(const float* __restrict__ w, __nv_bfloat16* __restrict__ Bt,
                        int OC, int IC) {
    int idx = blockIdx.x * 256 + threadIdx.x;
    if (idx >= OC * IC * 9) return;
    int K = IC * 9;
    int oc = idx / K, k = idx - oc * K;
    int ic = k / 9, tap = k - ic * 9;
    float v = w[idx];
    __nv_bfloat16 h = __float2bfloat16(v);
    float lo = v - __bfloat162float(h);
    size_t base = (((size_t)tap * OC + oc) * 2) * IC + ic;
    Bt[base]      = h;
    Bt[base + IC] = __float2bfloat16(lo);
}

// ---------------- implicit conv via WMMA, no im2col ----------------
// Full K per CTA (R9 structure). Per ic-chunk (64): stage fp32 halo tile
// [64][6][34], transpose/convert to bf16 hi/lo [pos][ic], 9 taps reuse it with
// shifted bases. B staged per tap with cp.async, double-buffered across the
// whole tap sequence (prefetch next tap during current mma).
// EPI 0: conv1 epilogue (g_xg + bias + pos). EPI 1: conv2 unpatch (g_u + bias).
// smem layout (bytes):
//   [0, 53504)           s32 [64][209] f32       (epilogue overlays sD [128][132] f32)
//   [53504, 82880)       sAh [204][72] bf16
//   [82880, 112256)      sAl [204][72] bf16
//   [112256, 185984)     sB: 2 bufs x (hi 18432 + lo 18432)
template<int IC, int EPI>
__global__ void __launch_bounds__(512) k_conv(const float* __restrict__ Xg,
                                              const __nv_bfloat16* __restrict__ Bt,
                                              const float* __restrict__ bias,
                                              const float* __restrict__ pos) {
    extern __shared__ __align__(16) char smem[];
    const int OC   = (EPI == 0) ? 128 : 448;
    const int S32L = 209;
    const int LDA  = 72;
    float* s32         = (float*)smem;
    __nv_bfloat16* sAh = (__nv_bfloat16*)(smem + 53504);
    __nv_bfloat16* sAl = (__nv_bfloat16*)(smem + 82880);
    float* sD          = (float*)smem;
    const uint32_t bB  = smem_u32(smem) + 112256u;   // B buffers base

    int t = threadIdx.x;
    int w = t >> 5;
    int wm = w >> 2, wn = w & 3;
    int bx = blockIdx.x;
    int img = bx >> 3, rb = bx & 7;
    int y0 = rb * 4;
    int m0 = bx * 128;
    int n0 = (EPI == 0) ? 0 : (int)blockIdx.y * 128;
    const int NCH = IC / 64;
    const int total_taps = NCH * 9;

    // pre-zero invalid B rows (conv2 last N-tile); never overwritten by cp.async
    if (n0 + 127 >= OC) {
        for (int idx = t; idx < 4096; idx += 512) {
            int seg = idx & 7;
            int row = (idx >> 3) & 127;
            int sel = (idx >> 10) & 1;
            int b2  = idx >> 11;
            if (n0 + row >= OC) {
                uint4 z; z.x = 0u; z.y = 0u; z.z = 0u; z.w = 0u;
                *(uint4*)(smem + 112256 + b2 * 36864 + sel * 18432
                          + (row * LDA + seg * 8) * 2) = z;
            }
        }
    }

    wmma::fragment<wmma::accumulator, 16, 16, 16, float> acc[2][2];
#pragma unroll
    for (int i = 0; i < 2; ++i)
#pragma unroll
        for (int j = 0; j < 2; ++j) wmma::fill_fragment(acc[i][j], 0.f);

    // stage B(tap) for chunk ch into buffer bsel via cp.async (16B granules)
    auto stageB = [&](int ch, int tap, int bsel) {
#pragma unroll
        for (int i = 0; i < 4; ++i) {
            int idx = t + i * 512;
            int seg = idx & 7;
            int row = (idx >> 3) & 127;
            int sel = idx >> 10;
            int oc  = n0 + row;
            if (oc < OC) {
                const __nv_bfloat16* src =
                    Bt + (((size_t)tap * OC + oc) * 2 + sel) * IC + ch * 64 + seg * 8;
                cp16(bB + (uint32_t)(bsel * 36864 + sel * 18432 + (row * LDA + seg * 8) * 2),
                     src);
            }
        }
    };

    // prologue prefetch: tap 0 of chunk 0 into buf 0
    stageB(0, 0, 0);
    cp_commit();
    int buf = 0;

    for (int ch = 0; ch < NCH; ++ch) {
        // ---- stage fp32 halo tile ----
        for (int idx = t; idx < 64 * 204; idx += 512) {
            int c  = idx / 204;
            int rr = idx - c * 204;
            int ry = rr / 34, cx = rr - ry * 34;
            int y = y0 - 1 + ry;
            int x = cx - 1;
            float v = 0.f;
            if (y >= 0 && y < 32 && x >= 0 && x < 32)
                v = Xg[((size_t)(img * IC + ch * 64 + c) << 10) + (y << 5) + x];
            s32[c * S32L + rr] = v;
        }
        __syncthreads();   // prev chunk's mma done before sA rewrite
        // ---- transpose + hi/lo convert ----
        for (int idx = t; idx < 8 * 204; idx += 512) {
            int icg = idx / 204;
            int p   = idx - icg * 204;
            uint4 vh, vl;
            uint32_t hw[4], lw[4];
#pragma unroll
            for (int pr = 0; pr < 4; ++pr) {
                float v0 = s32[(icg * 8 + pr * 2 + 0) * S32L + p];
                float v1 = s32[(icg * 8 + pr * 2 + 1) * S32L + p];
                __nv_bfloat16 h0 = __float2bfloat16(v0);
                __nv_bfloat16 h1 = __float2bfloat16(v1);
                __nv_bfloat16 l0 = __float2bfloat16(v0 - __bfloat162float(h0));
                __nv_bfloat16 l1 = __float2bfloat16(v1 - __bfloat162float(h1));
                hw[pr] = (uint32_t)__bfloat16_as_ushort(h0)
                       | ((uint32_t)__bfloat16_as_ushort(h1) << 16);
                lw[pr] = (uint32_t)__bfloat16_as_ushort(l0)
                       | ((uint32_t)__bfloat16_as_ushort(l1) << 16);
            }
            vh.x = hw[0]; vh.y = hw[1]; vh.z = hw[2]; vh.w = hw[3];
            vl.x = lw[0]; vl.y = lw[1]; vl.z = lw[2]; vl.w = lw[3];
            *(uint4*)&sAh[p * LDA + icg * 8] = vh;
            *(uint4*)&sAl[p * LDA + icg * 8] = vl;
        }
        __syncthreads();
        // ---- 9 taps, B double-buffered ----
        for (int tap = 0; tap < 9; ++tap) {
            cp_wait_all();
            __syncthreads();
            int g = ch * 9 + tap;
            if (g + 1 < total_taps) {
                int gn = g + 1;
                stageB(gn / 9, gn - (gn / 9) * 9, buf ^ 1);
            }
            cp_commit();
            __nv_bfloat16* sBh = (__nv_bfloat16*)(smem + 112256 + buf * 36864);
            __nv_bfloat16* sBl = sBh + 9216;   // 18432 B
            int dy = tap / 3 - 1, dx = tap - (tap / 3) * 3 - 1;
            int abase = ((1 + dy + wm) * 34 + (1 + dx)) * LDA;
#pragma unroll
            for (int ks = 0; ks < 4; ++ks) {
                int kk = ks * 16;
                wmma::fragment<wmma::matrix_a, 16, 16, 16, __nv_bfloat16, wmma::row_major> ah[2], al[2];
                wmma::fragment<wmma::matrix_b, 16, 16, 16, __nv_bfloat16, wmma::col_major> bh[2], bl[2];
                wmma::load_matrix_sync(ah[0], sAh + abase + 0  * LDA + kk, LDA);
                wmma::load_matrix_sync(ah[1], sAh + abase + 16 * LDA + kk, LDA);
                wmma::load_matrix_sync(al[0], sAl + abase + 0  * LDA + kk, LDA);
                wmma::load_matrix_sync(al[1], sAl + abase + 16 * LDA + kk, LDA);
                wmma::load_matrix_sync(bh[0], sBh + (wn * 32 + 0)  * LDA + kk, LDA);
                wmma::load_matrix_sync(bh[1], sBh + (wn * 32 + 16) * LDA + kk, LDA);
                wmma::load_matrix_sync(bl[0], sBl + (wn * 32 + 0)  * LDA + kk, LDA);
                wmma::load_matrix_sync(bl[1], sBl + (wn * 32 + 16) * LDA + kk, LDA);
#pragma unroll
                for (int i = 0; i < 2; ++i)
#pragma unroll
                    for (int j = 0; j < 2; ++j) {
                        wmma::mma_sync(acc[i][j], ah[i], bh[j], acc[i][j]);
                        wmma::mma_sync(acc[i][j], ah[i], bl[j], acc[i][j]);
                        wmma::mma_sync(acc[i][j], al[i], bh[j], acc[i][j]);
                    }
            }
            __syncthreads();
            buf ^= 1;
        }
    }

    // ---- epilogue: dump accumulators to smem f32 tile, scatter ----
#pragma unroll
    for (int i = 0; i < 2; ++i)
#pragma unroll
        for (int j = 0; j < 2; ++j)
            wmma::store_matrix_sync(sD + (wm * 32 + i * 16) * 132 + wn * 32 + j * 16,
                                    acc[i][j], 132, wmma::mem_row_major);
    __syncthreads();

    int r = t & 127, q = t >> 7;
    int px = m0 + r;
    const float* drow = sD + r * 132 + q * 32;
    if (EPI == 0) {
        int im = px >> 10, p = px & 1023;
        int bb = im / 3, ss = im - bb * 3;
        float* dst = g_xg + bb * 393216 + ss * 131072 + p;
#pragma unroll
        for (int c = 0; c < 32; ++c) {
            int oc = q * 32 + c;
            dst[oc * 1024] = drow[c] + bias[oc] + pos[oc * 1024 + p];
        }
    } else {
        int im = px >> 10, p = px & 1023;
        int y = p >> 5, xg = p & 31;
#pragma unroll
        for (int c = 0; c < 32; ++c) {
            int oc = n0 + q * 32 + c;
            if (oc < 448) {
                int p1 = oc / 56, rr2 = oc - p1 * 56;
                int p2 = rr2 / 7, e = rr2 - p2 * 7;
                g_u[((size_t)(im * 7 + e) * 256 + (size_t)(y * 8 + p1)) * 256
                    + (size_t)(xg * 8 + p2)] = drow[c] + bias[oc];
            }
        }
    }
}

// ---------------- K3: GroupNorm stats (64 contiguous groups of 24576) ----------------
__global__ void k_gnstats() {
    int bg = blockIdx.x;
    const float* p = g_xg + bg * 24576;
    int t = threadIdx.x;
    float s = 0.f, s2 = 0.f;
    for (int i = t; i < 24576; i += 256) { float v = p[i]; s += v; s2 += v * v; }
    __shared__ float rs[256], rq[256];
    rs[t] = s; rq[t] = s2; __syncthreads();
    for (int off = 128; off > 0; off >>= 1) {
        if (t < off) { rs[t] += rs[t + off]; rq[t] += rq[t + off]; }
        __syncthreads();
    }
    if (t == 0) {
        float mu = rs[0] * (1.f / 24576.f);
        float var = rq[0] * (1.f / 24576.f) - mu * mu;
        g_gn_mu[bg] = mu;
        g_gn_rs[bg] = rsqrtf(var + EPSV);
    }
}

// ---------------- K4: S-collapse with GN applied ----------------
__global__ void k_xq(const float* __restrict__ gamma, const float* __restrict__ beta,
                     const float* __restrict__ w2) {
    int idx = blockIdx.x * 256 + threadIdx.x;
    if (idx >= 4096 * 128) return;
    int nq = idx >> 7, dq = idx & 127;
    int b = nq >> 10;
    int fbase = (nq & 1023) * 384 + dq * 3;
    const float* xb = g_xg + b * 393216;
    float accv = 0.f;
#pragma unroll
    for (int sq = 0; sq < 3; ++sq) {
        int f  = fbase + sq;
        int dp = f / 3072;
        int gi = b * 16 + f / 24576;
        float v = xb[f];
        float xn = (v - g_gn_mu[gi]) * g_gn_rs[gi] * gamma[dp] + beta[dp];
        accv = fmaf(w2[sq], xn, accv);
    }
    g_xq[idx] = accv;
}

// ---------------- K5: q GEMM (4096x128 @ 128x256) ----------------
__global__ void __launch_bounds__(256) k_qgemm(const float* __restrict__ w1,
                                               const float* __restrict__ b1,
                                               const float* __restrict__ w2,
                                               const float* __restrict__ b2p) {
    __shared__ float As[64 * 68];
    __shared__ float Bs[64 * 68];
    int r0 = blockIdx.x * 64, o0 = blockIdx.y * 64;
    int t = threadIdx.x;
    int cth = (t & 15) * 4, rth = (t >> 4) * 4;
    float acc[4][4];
#pragma unroll
    for (int a = 0; a < 4; ++a)
#pragma unroll
        for (int c = 0; c < 4; ++c) acc[a][c] = 0.f;

    for (int k0 = 0; k0 < 128; k0 += 64) {
        __syncthreads();
        for (int idx = t; idx < 4096; idx += 256) {
            int jj = idx & 63, rr = idx >> 6;
            As[jj * 68 + rr] = g_xq[(r0 + rr) * 128 + k0 + jj];
            Bs[jj * 68 + rr] = w1[(o0 + rr) * 128 + k0 + jj];
        }
        __syncthreads();
#pragma unroll 8
        for (int j = 0; j < 64; ++j) {
            float4 av = *(const float4*)&As[j * 68 + rth];
            float4 bv = *(const float4*)&Bs[j * 68 + cth];
            float a[4] = {av.x, av.y, av.z, av.w};
            float bb[4] = {bv.x, bv.y, bv.z, bv.w};
#pragma unroll
            for (int r = 0; r < 4; ++r)
#pragma unroll
                for (int c = 0; c < 4; ++c) acc[r][c] = fmaf(a[r], bb[c], acc[r][c]);
        }
    }
    float w2s = w2[0] + w2[1] + w2[2];
    float b2v = b2p[0];
#pragma unroll
    for (int r = 0; r < 4; ++r)
#pragma unroll
        for (int c = 0; c < 4; ++c) {
            int o = o0 + cth + c;
            g_q[(r0 + rth + r) * 256 + o] = acc[r][c] + b1[o] * w2s + b2v;
        }
}

// ---------------- K6: per-row attention (16384 rows) ----------------
__global__ void __launch_bounds__(128) k_attn(const float* __restrict__ kc,
                                              const float* __restrict__ vc) {
    int n = blockIdx.x;
    int t = threadIdx.x;
    int lane = t & 31, wid = t >> 5;
    __shared__ float attn_s[128];
    __shared__ float red[128];

    const float* qp = g_q + (size_t)(n >> 2) * 256 + (n & 3) * 64;
    float2 q2 = *(const float2*)(qp + 2 * lane);
    const float* kb = kc + (size_t)n * 8192;

#pragma unroll 4
    for (int i = 0; i < 32; ++i) {
        int l = wid * 32 + i;
        float2 kv = *(const float2*)(kb + l * 64 + 2 * lane);
        float p = q2.x * kv.x + q2.y * kv.y;
        p += __shfl_xor_sync(0xffffffffu, p, 16);
        p += __shfl_xor_sync(0xffffffffu, p, 8);
        p += __shfl_xor_sync(0xffffffffu, p, 4);
        p += __shfl_xor_sync(0xffffffffu, p, 2);
        p += __shfl_xor_sync(0xffffffffu, p, 1);
        if (lane == i) attn_s[l] = p * 0.125f;
    }
    __syncthreads();

    float v = attn_s[t];
    float m = v;
    m = fmaxf(m, __shfl_xor_sync(0xffffffffu, m, 16));
    m = fmaxf(m, __shfl_xor_sync(0xffffffffu, m, 8));
    m = fmaxf(m, __shfl_xor_sync(0xffffffffu, m, 4));
    m = fmaxf(m, __shfl_xor_sync(0xffffffffu, m, 2));
    m = fmaxf(m, __shfl_xor_sync(0xffffffffu, m, 1));
    if (lane == 0) red[wid] = m;
    __syncthreads();
    float bm = fmaxf(fmaxf(red[0], red[1]), fmaxf(red[2], red[3]));
    float e = expf(v - bm);
    float s = e;
    s += __shfl_xor_sync(0xffffffffu, s, 16);
    s += __shfl_xor_sync(0xffffffffu, s, 8);
    s += __shfl_xor_sync(0xffffffffu, s, 4);
    s += __shfl_xor_sync(0xffffffffu, s, 2);
    s += __shfl_xor_sync(0xffffffffu, s, 1);
    __syncthreads();
    if (lane == 0) red[wid] = s;
    __syncthreads();
    float bs = red[0] + red[1] + red[2] + red[3];
    attn_s[t] = e * (1.f / bs);
    __syncthreads();

    int c = t & 31, chunk = t >> 5;
    const float* vb = vc + (size_t)n * 4096;
    float acc = 0.f;
#pragma unroll 8
    for (int i = 0; i < 32; ++i) {
        int l = chunk * 32 + i;
        acc = fmaf(attn_s[l], vb[l * 32 + c], acc);
    }
    __syncthreads();
    red[t] = acc;
    __syncthreads();
    if (t < 32) {
        float o = red[t] + red[32 + t] + red[64 + t] + red[96 + t];
        g_oflat[(n & 4095) * 128 + (n >> 12) * 32 + t] = o;
    }
}

// ---------------- K7: outproj 128x128 per-pixel matvec ----------------
__global__ void __launch_bounds__(256) k_outproj(const float* __restrict__ w,
                                                 const float* __restrict__ bias) {
    __shared__ float in_s[32 * 128];
    __shared__ float w_s[32 * 36];
    int b = blockIdx.x >> 3, pt = blockIdx.x & 7;
    int oc0 = blockIdx.y * 32;
    int t = threadIdx.x;
    int tx = t & 15, ty = t >> 4;
    int p0 = tx * 8, ol = ty * 2;
    float acc[2][8];
#pragma unroll
    for (int j = 0; j < 2; ++j)
#pragma unroll
        for (int i = 0; i < 8; ++i) acc[j][i] = 0.f;

    for (int c0 = 0; c0 < 128; c0 += 32) {
        __syncthreads();
        for (int idx = t; idx < 32 * 128; idx += 256) {
            int c = idx >> 7, p = idx & 127;
            in_s[idx] = g_oflat[b * 131072 + (c0 + c) * 1024 + pt * 128 + p];
        }
        for (int idx = t; idx < 32 * 32; idx += 256) {
            int c = idx & 31, o = idx >> 5;
            w_s[c * 36 + o] = w[(oc0 + o) * 128 + c0 + c];
        }
        __syncthreads();
#pragma unroll 4
        for (int c = 0; c < 32; ++c) {
            float w0 = w_s[c * 36 + ol], w1 = w_s[c * 36 + ol + 1];
            float4 i0 = *(const float4*)&in_s[c * 128 + p0];
            float4 i1 = *(const float4*)&in_s[c * 128 + p0 + 4];
            float iv[8] = {i0.x, i0.y, i0.z, i0.w, i1.x, i1.y, i1.z, i1.w};
#pragma unroll
            for (int i = 0; i < 8; ++i) {
                acc[0][i] = fmaf(w0, iv[i], acc[0][i]);
                acc[1][i] = fmaf(w1, iv[i], acc[1][i]);
            }
        }
    }
#pragma unroll
    for (int j = 0; j < 2; ++j) {
        int oc = oc0 + ol + j;
        float bv = bias[oc];
#pragma unroll
        for (int i = 0; i < 8; ++i)
            g_o2[(b * 128 + oc) * 1024 + pt * 128 + p0 + i] = acc[j][i] + bv;
    }
}

// ---------------- K9: modulation ----------------
__global__ void k_mod(const float* __restrict__ emb, const float* __restrict__ mw,
                      const float* __restrict__ mb) {
    int t = threadIdx.x;
    if (t < 56) {
        int b = t / 14, o = t % 14;
        float accv = mb[o];
        for (int k = 0; k < 256; ++k) {
            float e = emb[b * 256 + k];
            float si = e / (1.f + expf(-e));
            accv = fmaf(si, mw[o * 256 + k], accv);
        }
        g_mod[t] = accv;
    }
}

// ---------------- K10/K11: LayerNorm over u per batch ----------------
__global__ void k_lnpart() {
    int bidx = blockIdx.x;
    int b = bidx >> 5, part = bidx & 31;
    const float* p = g_u + b * 458752 + part * 14336;
    int t = threadIdx.x;
    float s = 0.f, s2 = 0.f;
    for (int i = t; i < 14336; i += 256) { float v = p[i]; s += v; s2 += v * v; }
    __shared__ float rs[256], rq[256];
    rs[t] = s; rq[t] = s2; __syncthreads();
    for (int off = 128; off > 0; off >>= 1) {
        if (t < off) { rs[t] += rs[t + off]; rq[t] += rq[t + off]; }
        __syncthreads();
    }
    if (t == 0) { g_lnp[bidx * 2] = rs[0]; g_lnp[bidx * 2 + 1] = rq[0]; }
}

__global__ void k_lnfin() {
    int t = threadIdx.x;
    if (t < 4) {
        float s = 0.f, s2 = 0.f;
        for (int i = 0; i < 32; ++i) {
            s  += g_lnp[(t * 32 + i) * 2];
            s2 += g_lnp[(t * 32 + i) * 2 + 1];
        }
        float mu = s * (1.f / 458752.f);
        float var = s2 * (1.f / 458752.f) - mu * mu;
        g_ln[t * 2] = mu;
        g_ln[t * 2 + 1] = rsqrtf(var + EPSV);
    }
}

// ---------------- K12: final elementwise tail ----------------
__device__ __forceinline__ float gelu_exact(float x) {
    return 0.5f * x * (1.f + erff(x * 0.70710678118654752f));
}

__global__ void k_final(const float* __restrict__ ew, const float* __restrict__ eb,
                        const float* __restrict__ fw, const float* __restrict__ fb,
                        float* __restrict__ out) {
    int gid = blockIdx.x * 256 + threadIdx.x;
    if (gid >= 262144) return;
    int b = gid >> 16, p = gid & 65535;
    float mu = g_ln[b * 2], rsd = g_ln[b * 2 + 1];
    float uv[7], un[7];
#pragma unroll
    for (int e = 0; e < 7; ++e) {
        uv[e] = g_u[b * 458752 + e * 65536 + p];
        float sc = g_mod[b * 14 + e];
        float sh = g_mod[b * 14 + 7 + e];
        un[e] = (uv[e] - mu) * rsd * (1.f + sc) + sh;
    }
    float en[14];
#pragma unroll
    for (int o = 0; o < 14; ++o) {
        float a = eb[o];
#pragma unroll
        for (int e = 0; e < 7; ++e) a = fmaf(ew[o * 7 + e], un[e], a);
        en[o] = a;
    }
    float hf[7];
#pragma unroll
    for (int e = 0; e < 7; ++e)
        hf[e] = gelu_exact(un[e]) + en[e] * gelu_exact(en[7 + e]);
#pragma unroll
    for (int o = 0; o < 7; ++o) {
        float a = fb[o];
#pragma unroll
        for (int e = 0; e < 7; ++e) a = fmaf(fw[o * 7 + e], hf[e], a);
        out[b * 458752 + o * 65536 + p] = a + uv[o];
    }
}

// ---------------- launch ----------------
extern "C" void kernel_launch(void* const* d_in, const int* in_sizes, int n_in,
                              void* d_out, int out_size) {
    const float* x    = (const float*)d_in[0];
    const float* kc   = (const float*)d_in[1];
    const float* vc   = (const float*)d_in[2];
    const float* emb  = (const float*)d_in[3];
    const float* pos  = (const float*)d_in[4];
    const float* pw   = (const float*)d_in[5];
    const float* pb   = (const float*)d_in[6];
    const float* gg   = (const float*)d_in[7];
    const float* gb   = (const float*)d_in[8];
    const float* w1   = (const float*)d_in[9];
    const float* b1   = (const float*)d_in[10];
    const float* w2   = (const float*)d_in[11];
    const float* b2   = (const float*)d_in[12];
    const float* ow   = (const float*)d_in[13];
    const float* ob   = (const float*)d_in[14];
    const float* uw   = (const float*)d_in[15];
    const float* ub   = (const float*)d_in[16];
    const float* mw   = (const float*)d_in[17];
    const float* mb   = (const float*)d_in[18];
    const float* ew   = (const float*)d_in[19];
    const float* ebb  = (const float*)d_in[20];
    const float* fw   = (const float*)d_in[21];
    const float* fb   = (const float*)d_in[22];
    float* out = (float*)d_out;

    const int DSMEM = 185984;
    cudaFuncSetAttribute(k_conv<448, 0>,
                         cudaFuncAttributeMaxDynamicSharedMemorySize, DSMEM);
    cudaFuncSetAttribute(k_conv<128, 1>,
                         cudaFuncAttributeMaxDynamicSharedMemorySize, DSMEM);

    __nv_bfloat16 *pBt1, *pBt2;
    cudaGetSymbolAddress((void**)&pBt1, g_Bt1);
    cudaGetSymbolAddress((void**)&pBt2, g_Bt2);
    float* pXin; cudaGetSymbolAddress((void**)&pXin, g_xin);
    float* pO2;  cudaGetSymbolAddress((void**)&pO2,  g_o2);

    k_patchify<<<5376, 256>>>(x);
    k_prepT<<<(128 * 448 * 9 + 255) / 256, 256>>>(pw, pBt1, 128, 448);
    k_prepT<<<(448 * 128 * 9 + 255) / 256, 256>>>(uw, pBt2, 448, 128);
    k_conv<448, 0><<<dim3(96, 1), 512, DSMEM>>>(pXin, pBt1, pb, pos);
    k_gnstats<<<64, 256>>>();
    k_xq<<<2048, 256>>>(gg, gb, w2);
    k_qgemm<<<dim3(64, 4), 256>>>(w1, b1, w2, b2);
    k_attn<<<16384, 128>>>(kc, vc);
    k_outproj<<<dim3(32, 4), 256>>>(ow, ob);
    k_conv<128, 1><<<dim3(32, 4), 512, DSMEM>>>(pO2, pBt2, ub, (const float*)0);
    k_mod<<<1, 64>>>(emb, mw, mb);
    k_lnpart<<<128, 256>>>();
    k_lnfin<<<1, 32>>>();
    k_final<<<1024, 256>>>(ew, ebb, fw, fb, out);
}

// round 14
// speedup vs baseline: 1.0628x; 1.0118x over previous
#include <cuda_runtime.h>
#include <cuda_bf16.h>
#include <mma.h>
#include <cstdint>
#include <math.h>

using namespace nvcuda;

// ---------------- problem constants ----------------
// B=4 S=3 E=7 IMG=256 PH=8 H=32 D=128 NH=4 DK=64 DC=128 DH=32 TEMB=256 LK=128 GROUPS=16
#define EPSV 1e-5f

// ---------------- scratch buffers (device globals; no allocation) ----------------
__device__ float g_xin [12 * 448 * 1024];   // patchified input (12,448,32,32)
__device__ float g_xg  [4 * 393216];        // conv1 out in xg flat layout (B, 393216)
__device__ float g_gn_mu[64];
__device__ float g_gn_rs[64];
__device__ float g_xq  [4096 * 128];        // S-collapsed normalized features
__device__ float g_q   [4096 * 256];        // query projections
__device__ float g_oflat[4096 * 128];       // attention output, (Nq, DC) flat
__device__ float g_o2  [4 * 128 * 1024];    // outproj output as (4,128,32,32)
__device__ float g_u   [4 * 7 * 65536];     // unpatched image (B,E,256,256) == skip
__device__ float g_mod [4 * 14];
__device__ float g_lnp [4 * 32 * 2];
__device__ float g_ln  [4 * 2];             // per-batch mu, rstd

// tap-major weights for implicit conv: Bt[tap][oc][hi(IC)|lo(IC)] bf16
__device__ __align__(16) __nv_bfloat16 g_Bt1[9ull * 128 * 2 * 448];  // 2 MB
__device__ __align__(16) __nv_bfloat16 g_Bt2[9ull * 448 * 2 * 128];  // 2 MB

// ---------------- helpers ----------------
__device__ __forceinline__ uint32_t smem_u32(const void* p) {
    return (uint32_t)__cvta_generic_to_shared(p);
}
__device__ __forceinline__ void cp16(uint32_t dst, const void* src) {
    asm volatile("cp.async.ca.shared.global [%0], [%1], 16;" :: "r"(dst), "l"(src));
}
__device__ __forceinline__ void cp_commit() {
    asm volatile("cp.async.commit_group;" ::: "memory");
}
__device__ __forceinline__ void cp_wait_all() {
    asm volatile("cp.async.wait_group 0;" ::: "memory");
}

// ---------------- K1: patchify (smem transpose, both sides coalesced) ----------------
__global__ void __launch_bounds__(256) k_patchify(const float* __restrict__ x) {
    __shared__ float s[1024];
    int blk    = blockIdx.x;        // 12*7*64
    int rowblk = blk & 63;          // group of 4 input rows
    int ime    = blk >> 6;          // img*7 + e
    int img = ime / 7, e = ime % 7;
    int t = threadIdx.x;
    const float* src = x + ((size_t)ime * 256 + rowblk * 4) * 256;
    s[t]       = src[t];
    s[t + 256] = src[t + 256];
    s[t + 512] = src[t + 512];
    s[t + 768] = src[t + 768];
    __syncthreads();
    int ph2 = t >> 5, xx = t & 31;
#pragma unroll
    for (int r = 0; r < 4; ++r) {
        int Y = rowblk * 4 + r;
        int ph1 = Y & 7, y = Y >> 3;
        int ic = ph1 * 56 + ph2 * 7 + e;
        g_xin[((img * 448 + ic) << 10) + (y << 5) + xx] = s[r * 256 + xx * 8 + ph2];
    }
}

// ---------------- weight prep: w[oc][ic*9+tap] fp32 -> Bt[tap][oc][hi|lo] bf16 ----------------
__global__ void k_prepT(const float* __restrict__ w, __nv_bfloat16* __restrict__ Bt,
                        int OC, int IC) {
    int idx = blockIdx.x * 256 + threadIdx.x;
    if (idx >= OC * IC * 9) return;
    int K = IC * 9;
    int oc = idx / K, k = idx - oc * K;
    int ic = k / 9, tap = k - ic * 9;
    float v = w[idx];
    __nv_bfloat16 h = __float2bfloat16(v);
    float lo = v - __bfloat162float(h);
    size_t base = (((size_t)tap * OC + oc) * 2) * IC + ic;
    Bt[base]      = h;
    Bt[base + IC] = __float2bfloat16(lo);
}

// ---------------- implicit conv via WMMA, no im2col ----------------
// M-tile = 64 px (2 output rows), 256 threads (8 warps, 2x4 grid, 32x32 warp tile).
// Per ic-chunk (64): DIRECT gmem->bf16 hi/lo transpose into sA [136 pos][72]
// (4 halo rows x 34 cols), then 9 taps reuse it with shifted bases. B staged per
// tap with cp.async double-buffered; ONE barrier per tap.
// 2 CTAs/SM (smem 112,896 B, launch_bounds(256,2)).
// EPI 0: conv1 epilogue (g_xg + bias + pos). EPI 1: conv2 unpatch (g_u + bias).
// smem layout (bytes):
//   [0, 19584)        sAh [136][72] bf16   (epilogue overlays sD [64][132] f32 = 33792)
//   [19584, 39168)    sAl [136][72] bf16
//   [39168, 112896)   sB: 2 bufs x (hi 18432 + lo 18432)
template<int IC, int EPI>
__global__ void __launch_bounds__(256, 2) k_conv(const float* __restrict__ Xg,
                                                 const __nv_bfloat16* __restrict__ Bt,
                                                 const float* __restrict__ bias,
                                                 const float* __restrict__ pos) {
    extern __shared__ __align__(16) char smem[];
    const int OC  = (EPI == 0) ? 128 : 448;
    const int LDA = 72;
    __nv_bfloat16* sAh = (__nv_bfloat16*)smem;
    __nv_bfloat16* sAl = (__nv_bfloat16*)(smem + 19584);
    float* sD          = (float*)smem;
    const uint32_t bB  = smem_u32(smem) + 39168u;

    int t = threadIdx.x;
    int w = t >> 5;
    int wm = w >> 2, wn = w & 3;        // 2 x 4 warp grid
    int bx = blockIdx.x;
    int img = bx >> 4, rb = bx & 15;    // 16 row-pairs per image
    int y0 = rb * 2;
    int m0 = bx * 64;
    int n0 = (EPI == 0) ? 0 : (int)blockIdx.y * 128;
    const int NCH = IC / 64;
    const int total_taps = NCH * 9;

    // pre-zero invalid B rows (conv2 last N-tile); never overwritten by cp.async
    if (n0 + 127 >= OC) {
        for (int idx = t; idx < 4096; idx += 256) {
            int seg = idx & 7;
            int row = (idx >> 3) & 127;
            int sel = (idx >> 10) & 1;
            int b2  = idx >> 11;
            if (n0 + row >= OC) {
                uint4 z; z.x = 0u; z.y = 0u; z.z = 0u; z.w = 0u;
                *(uint4*)(smem + 39168 + b2 * 36864 + sel * 18432
                          + (row * LDA + seg * 8) * 2) = z;
            }
        }
    }

    wmma::fragment<wmma::accumulator, 16, 16, 16, float> acc[2][2];
#pragma unroll
    for (int i = 0; i < 2; ++i)
#pragma unroll
        for (int j = 0; j < 2; ++j) wmma::fill_fragment(acc[i][j], 0.f);

    // stage B(tap) for chunk ch into buffer bsel (2048 x 16B via cp.async)
    auto stageB = [&](int ch, int tap, int bsel) {
#pragma unroll
        for (int i = 0; i < 8; ++i) {
            int idx = t + i * 256;
            int seg = idx & 7;
            int row = (idx >> 3) & 127;
            int sel = idx >> 10;
            int oc  = n0 + row;
            if (oc < OC) {
                const __nv_bfloat16* src =
                    Bt + (((size_t)tap * OC + oc) * 2 + sel) * IC + ch * 64 + seg * 8;
                cp16(bB + (uint32_t)(bsel * 36864 + sel * 18432 + (row * LDA + seg * 8) * 2),
                     src);
            }
        }
    };

    stageB(0, 0, 0);
    cp_commit();
    int buf = 0;

    for (int ch = 0; ch < NCH; ++ch) {
        __syncthreads();   // all warps done reading sA of previous chunk
        // ---- direct gmem -> bf16 hi/lo transpose: 8 icg x 136 pos ----
        for (int idx = t; idx < 1088; idx += 256) {
            int icg = idx / 136;
            int p   = idx - icg * 136;
            int ry = p / 34, cx = p - ry * 34;
            int y = y0 - 1 + ry;
            int x = cx - 1;
            bool ok = (y >= 0 && y < 32 && x >= 0 && x < 32);
            const float* basep =
                Xg + (((size_t)(img * IC + ch * 64 + icg * 8)) << 10) + (y << 5) + x;
            uint4 vh, vl;
            uint32_t hw[4], lw[4];
#pragma unroll
            for (int pr = 0; pr < 4; ++pr) {
                float v0 = ok ? basep[(size_t)(pr * 2 + 0) << 10] : 0.f;
                float v1 = ok ? basep[(size_t)(pr * 2 + 1) << 10] : 0.f;
                __nv_bfloat16 h0 = __float2bfloat16(v0);
                __nv_bfloat16 h1 = __float2bfloat16(v1);
                __nv_bfloat16 l0 = __float2bfloat16(v0 - __bfloat162float(h0));
                __nv_bfloat16 l1 = __float2bfloat16(v1 - __bfloat162float(h1));
                hw[pr] = (uint32_t)__bfloat16_as_ushort(h0)
                       | ((uint32_t)__bfloat16_as_ushort(h1) << 16);
                lw[pr] = (uint32_t)__bfloat16_as_ushort(l0)
                       | ((uint32_t)__bfloat16_as_ushort(l1) << 16);
            }
            vh.x = hw[0]; vh.y = hw[1]; vh.z = hw[2]; vh.w = hw[3];
            vl.x = lw[0]; vl.y = lw[1]; vl.z = lw[2]; vl.w = lw[3];
            *(uint4*)&sAh[p * LDA + icg * 8] = vh;
            *(uint4*)&sAl[p * LDA + icg * 8] = vl;
        }
        __syncthreads();   // sA ready
        // ---- 9 taps, B double-buffered, ONE barrier per tap ----
        for (int tap = 0; tap < 9; ++tap) {
            cp_wait_all();
            __syncthreads();
            int g = ch * 9 + tap;
            if (g + 1 < total_taps) {
                int gn = g + 1;
                stageB(gn / 9, gn - (gn / 9) * 9, buf ^ 1);
            }
            cp_commit();
            __nv_bfloat16* sBh = (__nv_bfloat16*)(smem + 39168 + buf * 36864);
            __nv_bfloat16* sBl = sBh + 9216;   // +18432 B
            int dy = tap / 3 - 1, dx = tap - (tap / 3) * 3 - 1;
            int abase = ((1 + dy + wm) * 34 + (1 + dx)) * LDA;
#pragma unroll
            for (int ks = 0; ks < 4; ++ks) {
                int kk = ks * 16;
                wmma::fragment<wmma::matrix_a, 16, 16, 16, __nv_bfloat16, wmma::row_major> ah[2], al[2];
                wmma::fragment<wmma::matrix_b, 16, 16, 16, __nv_bfloat16, wmma::col_major> bh[2], bl[2];
                wmma::load_matrix_sync(ah[0], sAh + abase + 0  * LDA + kk, LDA);
                wmma::load_matrix_sync(ah[1], sAh + abase + 16 * LDA + kk, LDA);
                wmma::load_matrix_sync(al[0], sAl + abase + 0  * LDA + kk, LDA);
                wmma::load_matrix_sync(al[1], sAl + abase + 16 * LDA + kk, LDA);
                wmma::load_matrix_sync(bh[0], sBh + (wn * 32 + 0)  * LDA + kk, LDA);
                wmma::load_matrix_sync(bh[1], sBh + (wn * 32 + 16) * LDA + kk, LDA);
                wmma::load_matrix_sync(bl[0], sBl + (wn * 32 + 0)  * LDA + kk, LDA);
                wmma::load_matrix_sync(bl[1], sBl + (wn * 32 + 16) * LDA + kk, LDA);
#pragma unroll
                for (int i = 0; i < 2; ++i)
#pragma unroll
                    for (int j = 0; j < 2; ++j) {
                        wmma::mma_sync(acc[i][j], ah[i], bh[j], acc[i][j]);
                        wmma::mma_sync(acc[i][j], ah[i], bl[j], acc[i][j]);
                        wmma::mma_sync(acc[i][j], al[i], bh[j], acc[i][j]);
                    }
            }
            buf ^= 1;
        }
    }

    // ---- epilogue: dump accumulators to smem f32 tile [64][132], scatter ----
    __syncthreads();   // all warps done with final LDSM before sD overlays sA
#pragma unroll
    for (int i = 0; i < 2; ++i)
#pragma unroll
        for (int j = 0; j < 2; ++j)
            wmma::store_matrix_sync(sD + (wm * 32 + i * 16) * 132 + wn * 32 + j * 16,
                                    acc[i][j], 132, wmma::mem_row_major);
    __syncthreads();

    int r = t & 63, q = t >> 6;        // 64 rows x 4 col-blocks of 32
    int px = m0 + r;
    const float* drow = sD + r * 132 + q * 32;
    if (EPI == 0) {
        int im = px >> 10, p = px & 1023;
        int bb = im / 3, ss = im - bb * 3;
        float* dst = g_xg + bb * 393216 + ss * 131072 + p;
#pragma unroll
        for (int c = 0; c < 32; ++c) {
            int oc = q * 32 + c;
            dst[oc * 1024] = drow[c] + bias[oc] + pos[oc * 1024 + p];
        }
    } else {
        int im = px >> 10, p = px & 1023;
        int y = p >> 5, xg = p & 31;
#pragma unroll
        for (int c = 0; c < 32; ++c) {
            int oc = n0 + q * 32 + c;
            if (oc < 448) {
                int p1 = oc / 56, rr2 = oc - p1 * 56;
                int p2 = rr2 / 7, e = rr2 - p2 * 7;
                g_u[((size_t)(im * 7 + e) * 256 + (size_t)(y * 8 + p1)) * 256
                    + (size_t)(xg * 8 + p2)] = drow[c] + bias[oc];
            }
        }
    }
}

// ---------------- K3: GroupNorm stats (64 contiguous groups of 24576) ----------------
__global__ void k_gnstats() {
    int bg = blockIdx.x;
    const float* p = g_xg + bg * 24576;
    int t = threadIdx.x;
    float s = 0.f, s2 = 0.f;
    for (int i = t; i < 24576; i += 256) { float v = p[i]; s += v; s2 += v * v; }
    __shared__ float rs[256], rq[256];
    rs[t] = s; rq[t] = s2; __syncthreads();
    for (int off = 128; off > 0; off >>= 1) {
        if (t < off) { rs[t] += rs[t + off]; rq[t] += rq[t + off]; }
        __syncthreads();
    }
    if (t == 0) {
        float mu = rs[0] * (1.f / 24576.f);
        float var = rq[0] * (1.f / 24576.f) - mu * mu;
        g_gn_mu[bg] = mu;
        g_gn_rs[bg] = rsqrtf(var + EPSV);
    }
}

// ---------------- K4: S-collapse with GN applied ----------------
__global__ void k_xq(const float* __restrict__ gamma, const float* __restrict__ beta,
                     const float* __restrict__ w2) {
    int idx = blockIdx.x * 256 + threadIdx.x;
    if (idx >= 4096 * 128) return;
    int nq = idx >> 7, dq = idx & 127;
    int b = nq >> 10;
    int fbase = (nq & 1023) * 384 + dq * 3;
    const float* xb = g_xg + b * 393216;
    float accv = 0.f;
#pragma unroll
    for (int sq = 0; sq < 3; ++sq) {
        int f  = fbase + sq;
        int dp = f / 3072;
        int gi = b * 16 + f / 24576;
        float v = xb[f];
        float xn = (v - g_gn_mu[gi]) * g_gn_rs[gi] * gamma[dp] + beta[dp];
        accv = fmaf(w2[sq], xn, accv);
    }
    g_xq[idx] = accv;
}

// ---------------- K5: q GEMM (4096x128 @ 128x256) ----------------
__global__ void __launch_bounds__(256) k_qgemm(const float* __restrict__ w1,
                                               const float* __restrict__ b1,
                                               const float* __restrict__ w2,
                                               const float* __restrict__ b2p) {
    __shared__ float As[64 * 68];
    __shared__ float Bs[64 * 68];
    int r0 = blockIdx.x * 64, o0 = blockIdx.y * 64;
    int t = threadIdx.x;
    int cth = (t & 15) * 4, rth = (t >> 4) * 4;
    float acc[4][4];
#pragma unroll
    for (int a = 0; a < 4; ++a)
#pragma unroll
        for (int c = 0; c < 4; ++c) acc[a][c] = 0.f;

    for (int k0 = 0; k0 < 128; k0 += 64) {
        __syncthreads();
        for (int idx = t; idx < 4096; idx += 256) {
            int jj = idx & 63, rr = idx >> 6;
            As[jj * 68 + rr] = g_xq[(r0 + rr) * 128 + k0 + jj];
            Bs[jj * 68 + rr] = w1[(o0 + rr) * 128 + k0 + jj];
        }
        __syncthreads();
#pragma unroll 8
        for (int j = 0; j < 64; ++j) {
            float4 av = *(const float4*)&As[j * 68 + rth];
            float4 bv = *(const float4*)&Bs[j * 68 + cth];
            float a[4] = {av.x, av.y, av.z, av.w};
            float bb[4] = {bv.x, bv.y, bv.z, bv.w};
#pragma unroll
            for (int r = 0; r < 4; ++r)
#pragma unroll
                for (int c = 0; c < 4; ++c) acc[r][c] = fmaf(a[r], bb[c], acc[r][c]);
        }
    }
    float w2s = w2[0] + w2[1] + w2[2];
    float b2v = b2p[0];
#pragma unroll
    for (int r = 0; r < 4; ++r)
#pragma unroll
        for (int c = 0; c < 4; ++c) {
            int o = o0 + cth + c;
            g_q[(r0 + rth + r) * 256 + o] = acc[r][c] + b1[o] * w2s + b2v;
        }
}

// ---------------- K6: per-row attention (16384 rows) ----------------
__global__ void __launch_bounds__(128) k_attn(const float* __restrict__ kc,
                                              const float* __restrict__ vc) {
    int n = blockIdx.x;
    int t = threadIdx.x;
    int lane = t & 31, wid = t >> 5;
    __shared__ float attn_s[128];
    __shared__ float red[128];

    const float* qp = g_q + (size_t)(n >> 2) * 256 + (n & 3) * 64;
    float2 q2 = *(const float2*)(qp + 2 * lane);
    const float* kb = kc + (size_t)n * 8192;

#pragma unroll 4
    for (int i = 0; i < 32; ++i) {
        int l = wid * 32 + i;
        float2 kv = *(const float2*)(kb + l * 64 + 2 * lane);
        float p = q2.x * kv.x + q2.y * kv.y;
        p += __shfl_xor_sync(0xffffffffu, p, 16);
        p += __shfl_xor_sync(0xffffffffu, p, 8);
        p += __shfl_xor_sync(0xffffffffu, p, 4);
        p += __shfl_xor_sync(0xffffffffu, p, 2);
        p += __shfl_xor_sync(0xffffffffu, p, 1);
        if (lane == i) attn_s[l] = p * 0.125f;
    }
    __syncthreads();

    float v = attn_s[t];
    float m = v;
    m = fmaxf(m, __shfl_xor_sync(0xffffffffu, m, 16));
    m = fmaxf(m, __shfl_xor_sync(0xffffffffu, m, 8));
    m = fmaxf(m, __shfl_xor_sync(0xffffffffu, m, 4));
    m = fmaxf(m, __shfl_xor_sync(0xffffffffu, m, 2));
    m = fmaxf(m, __shfl_xor_sync(0xffffffffu, m, 1));
    if (lane == 0) red[wid] = m;
    __syncthreads();
    float bm = fmaxf(fmaxf(red[0], red[1]), fmaxf(red[2], red[3]));
    float e = expf(v - bm);
    float s = e;
    s += __shfl_xor_sync(0xffffffffu, s, 16);
    s += __shfl_xor_sync(0xffffffffu, s, 8);
    s += __shfl_xor_sync(0xffffffffu, s, 4);
    s += __shfl_xor_sync(0xffffffffu, s, 2);
    s += __shfl_xor_sync(0xffffffffu, s, 1);
    __syncthreads();
    if (lane == 0) red[wid] = s;
    __syncthreads();
    float bs = red[0] + red[1] + red[2] + red[3];
    attn_s[t] = e * (1.f / bs);
    __syncthreads();

    int c = t & 31, chunk = t >> 5;
    const float* vb = vc + (size_t)n * 4096;
    float acc = 0.f;
#pragma unroll 8
    for (int i = 0; i < 32; ++i) {
        int l = chunk * 32 + i;
        acc = fmaf(attn_s[l], vb[l * 32 + c], acc);
    }
    __syncthreads();
    red[t] = acc;
    __syncthreads();
    if (t < 32) {
        float o = red[t] + red[32 + t] + red[64 + t] + red[96 + t];
        g_oflat[(n & 4095) * 128 + (n >> 12) * 32 + t] = o;
    }
}

// ---------------- K7: outproj 128x128 per-pixel matvec ----------------
__global__ void __launch_bounds__(256) k_outproj(const float* __restrict__ w,
                                                 const float* __restrict__ bias) {
    __shared__ float in_s[32 * 128];
    __shared__ float w_s[32 * 36];
    int b = blockIdx.x >> 3, pt = blockIdx.x & 7;
    int oc0 = blockIdx.y * 32;
    int t = threadIdx.x;
    int tx = t & 15, ty = t >> 4;
    int p0 = tx * 8, ol = ty * 2;
    float acc[2][8];
#pragma unroll
    for (int j = 0; j < 2; ++j)
#pragma unroll
        for (int i = 0; i < 8; ++i) acc[j][i] = 0.f;

    for (int c0 = 0; c0 < 128; c0 += 32) {
        __syncthreads();
        for (int idx = t; idx < 32 * 128; idx += 256) {
            int c = idx >> 7, p = idx & 127;
            in_s[idx] = g_oflat[b * 131072 + (c0 + c) * 1024 + pt * 128 + p];
        }
        for (int idx = t; idx < 32 * 32; idx += 256) {
            int c = idx & 31, o = idx >> 5;
            w_s[c * 36 + o] = w[(oc0 + o) * 128 + c0 + c];
        }
        __syncthreads();
#pragma unroll 4
        for (int c = 0; c < 32; ++c) {
            float w0 = w_s[c * 36 + ol], w1 = w_s[c * 36 + ol + 1];
            float4 i0 = *(const float4*)&in_s[c * 128 + p0];
            float4 i1 = *(const float4*)&in_s[c * 128 + p0 + 4];
            float iv[8] = {i0.x, i0.y, i0.z, i0.w, i1.x, i1.y, i1.z, i1.w};
#pragma unroll
            for (int i = 0; i < 8; ++i) {
                acc[0][i] = fmaf(w0, iv[i], acc[0][i]);
                acc[1][i] = fmaf(w1, iv[i], acc[1][i]);
            }
        }
    }
#pragma unroll
    for (int j = 0; j < 2; ++j) {
        int oc = oc0 + ol + j;
        float bv = bias[oc];
#pragma unroll
        for (int i = 0; i < 8; ++i)
            g_o2[(b * 128 + oc) * 1024 + pt * 128 + p0 + i] = acc[j][i] + bv;
    }
}

// ---------------- K9: modulation ----------------
__global__ void k_mod(const float* __restrict__ emb, const float* __restrict__ mw,
                      const float* __restrict__ mb) {
    int t = threadIdx.x;
    if (t < 56) {
        int b = t / 14, o = t % 14;
        float accv = mb[o];
        for (int k = 0; k < 256; ++k) {
            float e = emb[b * 256 + k];
            float si = e / (1.f + expf(-e));
            accv = fmaf(si, mw[o * 256 + k], accv);
        }
        g_mod[t] = accv;
    }
}

// ---------------- K10/K11: LayerNorm over u per batch ----------------
__global__ void k_lnpart() {
    int bidx = blockIdx.x;
    int b = bidx >> 5, part = bidx & 31;
    const float* p = g_u + b * 458752 + part * 14336;
    int t = threadIdx.x;
    float s = 0.f, s2 = 0.f;
    for (int i = t; i < 14336; i += 256) { float v = p[i]; s += v; s2 += v * v; }
    __shared__ float rs[256], rq[256];
    rs[t] = s; rq[t] = s2; __syncthreads();
    for (int off = 128; off > 0; off >>= 1) {
        if (t < off) { rs[t] += rs[t + off]; rq[t] += rq[t + off]; }
        __syncthreads();
    }
    if (t == 0) { g_lnp[bidx * 2] = rs[0]; g_lnp[bidx * 2 + 1] = rq[0]; }
}

__global__ void k_lnfin() {
    int t = threadIdx.x;
    if (t < 4) {
        float s = 0.f, s2 = 0.f;
        for (int i = 0; i < 32; ++i) {
            s  += g_lnp[(t * 32 + i) * 2];
            s2 += g_lnp[(t * 32 + i) * 2 + 1];
        }
        float mu = s * (1.f / 458752.f);
        float var = s2 * (1.f / 458752.f) - mu * mu;
        g_ln[t * 2] = mu;
        g_ln[t * 2 + 1] = rsqrtf(var + EPSV);
    }
}

// ---------------- K12: final elementwise tail ----------------
__device__ __forceinline__ float gelu_exact(float x) {
    return 0.5f * x * (1.f + erff(x * 0.70710678118654752f));
}

__global__ void k_final(const float* __restrict__ ew, const float* __restrict__ eb,
                        const float* __restrict__ fw, const float* __restrict__ fb,
                        float* __restrict__ out) {
    int gid = blockIdx.x * 256 + threadIdx.x;
    if (gid >= 262144) return;
    int b = gid >> 16, p = gid & 65535;
    float mu = g_ln[b * 2], rsd = g_ln[b * 2 + 1];
    float uv[7], un[7];
#pragma unroll
    for (int e = 0; e < 7; ++e) {
        uv[e] = g_u[b * 458752 + e * 65536 + p];
        float sc = g_mod[b * 14 + e];
        float sh = g_mod[b * 14 + 7 + e];
        un[e] = (uv[e] - mu) * rsd * (1.f + sc) + sh;
    }
    float en[14];
#pragma unroll
    for (int o = 0; o < 14; ++o) {
        float a = eb[o];
#pragma unroll
        for (int e = 0; e < 7; ++e) a = fmaf(ew[o * 7 + e], un[e], a);
        en[o] = a;
    }
    float hf[7];
#pragma unroll
    for (int e = 0; e < 7; ++e)
        hf[e] = gelu_exact(un[e]) + en[e] * gelu_exact(en[7 + e]);
#pragma unroll
    for (int o = 0; o < 7; ++o) {
        float a = fb[o];
#pragma unroll
        for (int e = 0; e < 7; ++e) a = fmaf(fw[o * 7 + e], hf[e], a);
        out[b * 458752 + o * 65536 + p] = a + uv[o];
    }
}

// ---------------- launch ----------------
extern "C" void kernel_launch(void* const* d_in, const int* in_sizes, int n_in,
                              void* d_out, int out_size) {
    const float* x    = (const float*)d_in[0];
    const float* kc   = (const float*)d_in[1];
    const float* vc   = (const float*)d_in[2];
    const float* emb  = (const float*)d_in[3];
    const float* pos  = (const float*)d_in[4];
    const float* pw   = (const float*)d_in[5];
    const float* pb   = (const float*)d_in[6];
    const float* gg   = (const float*)d_in[7];
    const float* gb   = (const float*)d_in[8];
    const float* w1   = (const float*)d_in[9];
    const float* b1   = (const float*)d_in[10];
    const float* w2   = (const float*)d_in[11];
    const float* b2   = (const float*)d_in[12];
    const float* ow   = (const float*)d_in[13];
    const float* ob   = (const float*)d_in[14];
    const float* uw   = (const float*)d_in[15];
    const float* ub   = (const float*)d_in[16];
    const float* mw   = (const float*)d_in[17];
    const float* mb   = (const float*)d_in[18];
    const float* ew   = (const float*)d_in[19];
    const float* ebb  = (const float*)d_in[20];
    const float* fw   = (const float*)d_in[21];
    const float* fb   = (const float*)d_in[22];
    float* out = (float*)d_out;

    const int DSMEM = 112896;
    cudaFuncSetAttribute(k_conv<448, 0>,
                         cudaFuncAttributeMaxDynamicSharedMemorySize, DSMEM);
    cudaFuncSetAttribute(k_conv<128, 1>,
                         cudaFuncAttributeMaxDynamicSharedMemorySize, DSMEM);

    __nv_bfloat16 *pBt1, *pBt2;
    cudaGetSymbolAddress((void**)&pBt1, g_Bt1);
    cudaGetSymbolAddress((void**)&pBt2, g_Bt2);
    float* pXin; cudaGetSymbolAddress((void**)&pXin, g_xin);
    float* pO2;  cudaGetSymbolAddress((void**)&pO2,  g_o2);

    k_patchify<<<5376, 256>>>(x);
    k_prepT<<<(128 * 448 * 9 + 255) / 256, 256>>>(pw, pBt1, 128, 448);
    k_prepT<<<(448 * 128 * 9 + 255) / 256, 256>>>(uw, pBt2, 448, 128);
    k_conv<448, 0><<<dim3(192, 1), 256, DSMEM>>>(pXin, pBt1, pb, pos);
    k_gnstats<<<64, 256>>>();
    k_xq<<<2048, 256>>>(gg, gb, w2);
    k_qgemm<<<dim3(64, 4), 256>>>(w1, b1, w2, b2);
    k_attn<<<16384, 128>>>(kc, vc);
    k_outproj<<<dim3(32, 4), 256>>>(ow, ob);
    k_conv<128, 1><<<dim3(64, 4), 256, DSMEM>>>(pO2, pBt2, ub, (const float*)0);
    k_mod<<<1, 64>>>(emb, mw, mb);
    k_lnpart<<<128, 256>>>();
    k_lnfin<<<1, 32>>>();
    k_final<<<1024, 256>>>(ew, ebb, fw, fb, out);
}

// round 15
// speedup vs baseline: 1.2027x; 1.1316x over previous
#include <cuda_runtime.h>
#include <cuda_bf16.h>
#include <mma.h>
#include <cstdint>
#include <math.h>

using namespace nvcuda;

// ---------------- problem constants ----------------
// B=4 S=3 E=7 IMG=256 PH=8 H=32 D=128 NH=4 DK=64 DC=128 DH=32 TEMB=256 LK=128 GROUPS=16
#define EPSV 1e-5f

// ---------------- scratch buffers (device globals; no allocation) ----------------
__device__ float g_xin [12 * 448 * 1024];   // patchified input (12,448,32,32)
__device__ float g_xg  [4 * 393216];        // conv1 out in xg flat layout (B, 393216)
__device__ float g_gn_mu[64];
__device__ float g_gn_rs[64];
__device__ float g_xq  [4096 * 128];        // S-collapsed normalized features
__device__ float g_q   [4096 * 256];        // query projections
__device__ float g_oflat[4096 * 128];       // attention output, (Nq, DC) flat
__device__ float g_o2  [4 * 128 * 1024];    // outproj output as (4,128,32,32)
__device__ float g_u   [4 * 7 * 65536];     // unpatched image (B,E,256,256) == skip
__device__ float g_mod [4 * 14];
__device__ float g_lnp [4 * 32 * 2];
__device__ float g_ln  [4 * 2];             // per-batch mu, rstd

// tap-major weights for implicit conv: Bt[tap][oc][hi(IC)|lo(IC)] bf16
__device__ __align__(16) __nv_bfloat16 g_Bt1[9ull * 128 * 2 * 448];  // 2 MB
__device__ __align__(16) __nv_bfloat16 g_Bt2[9ull * 448 * 2 * 128];  // 2 MB

// ---------------- helpers ----------------
__device__ __forceinline__ uint32_t smem_u32(const void* p) {
    return (uint32_t)__cvta_generic_to_shared(p);
}
__device__ __forceinline__ void cp16(uint32_t dst, const void* src) {
    asm volatile("cp.async.ca.shared.global [%0], [%1], 16;" :: "r"(dst), "l"(src));
}
__device__ __forceinline__ void cp_commit() {
    asm volatile("cp.async.commit_group;" ::: "memory");
}
__device__ __forceinline__ void cp_wait_all() {
    asm volatile("cp.async.wait_group 0;" ::: "memory");
}

// ---------------- K1: patchify (smem transpose, both sides coalesced) ----------------
__global__ void __launch_bounds__(256) k_patchify(const float* __restrict__ x) {
    __shared__ float s[1024];
    int blk    = blockIdx.x;        // 12*7*64
    int rowblk = blk & 63;          // group of 4 input rows
    int ime    = blk >> 6;          // img*7 + e
    int img = ime / 7, e = ime % 7;
    int t = threadIdx.x;
    const float* src = x + ((size_t)ime * 256 + rowblk * 4) * 256;
    s[t]       = src[t];
    s[t + 256] = src[t + 256];
    s[t + 512] = src[t + 512];
    s[t + 768] = src[t + 768];
    __syncthreads();
    int ph2 = t >> 5, xx = t & 31;
#pragma unroll
    for (int r = 0; r < 4; ++r) {
        int Y = rowblk * 4 + r;
        int ph1 = Y & 7, y = Y >> 3;
        int ic = ph1 * 56 + ph2 * 7 + e;
        g_xin[((img * 448 + ic) << 10) + (y << 5) + xx] = s[r * 256 + xx * 8 + ph2];
    }
}

// ---------------- weight prep: w[oc][ic*9+tap] fp32 -> Bt[tap][oc][hi|lo] bf16 ----------------
__global__ void k_prepT(const float* __restrict__ w, __nv_bfloat16* __restrict__ Bt,
                        int OC, int IC) {
    int idx = blockIdx.x * 256 + threadIdx.x;
    if (idx >= OC * IC * 9) return;
    int K = IC * 9;
    int oc = idx / K, k = idx - oc * K;
    int ic = k / 9, tap = k - ic * 9;
    float v = w[idx];
    __nv_bfloat16 h = __float2bfloat16(v);
    float lo = v - __bfloat162float(h);
    size_t base = (((size_t)tap * OC + oc) * 2) * IC + ic;
    Bt[base]      = h;
    Bt[base + IC] = __float2bfloat16(lo);
}

// ---------------- implicit conv via WMMA, no im2col ----------------
// M-tile = 64 px (2 output rows), N-tile = 64 oc, 128 threads (4 warps, 2x2 grid
// of 32x32 warp tiles). Per ic-chunk (64): direct gmem->bf16 hi/lo transpose into
// sA [136 pos][72]; 9 taps reuse it with shifted bases. B staged per tap with
// cp.async double-buffered; one barrier per tap. 3 CTAs/SM (smem 76,032 B).
// EPI 0: conv1 (OC=128, grid.y=2). EPI 1: conv2 (OC=448, grid.y=7, exact).
// smem layout (bytes):
//   [0, 19584)       sAh [136][72] bf16   (epilogue overlays sD [64][68] f32 = 17408)
//   [19584, 39168)   sAl [136][72] bf16
//   [39168, 76032)   sB: 2 bufs x (hi 9216 + lo 9216)
template<int IC, int EPI>
__global__ void __launch_bounds__(128, 3) k_conv(const float* __restrict__ Xg,
                                                 const __nv_bfloat16* __restrict__ Bt,
                                                 const float* __restrict__ bias,
                                                 const float* __restrict__ pos) {
    extern __shared__ __align__(16) char smem[];
    const int OC  = (EPI == 0) ? 128 : 448;
    const int LDA = 72;
    __nv_bfloat16* sAh = (__nv_bfloat16*)smem;
    __nv_bfloat16* sAl = (__nv_bfloat16*)(smem + 19584);
    float* sD          = (float*)smem;
    const uint32_t bB  = smem_u32(smem) + 39168u;

    int t = threadIdx.x;
    int w = t >> 5;
    int wm = w >> 1, wn = w & 1;        // 2 x 2 warp grid, 32x32 tiles
    int bx = blockIdx.x;
    int img = bx >> 4, rb = bx & 15;    // 16 row-pairs per image
    int y0 = rb * 2;
    int m0 = bx * 64;
    int n0 = (int)blockIdx.y * 64;
    const int NCH = IC / 64;
    const int total_taps = NCH * 9;

    wmma::fragment<wmma::accumulator, 16, 16, 16, float> acc[2][2];
#pragma unroll
    for (int i = 0; i < 2; ++i)
#pragma unroll
        for (int j = 0; j < 2; ++j) wmma::fill_fragment(acc[i][j], 0.f);

    // stage B(tap) for chunk ch into buffer bsel (1024 x 16B via cp.async)
    auto stageB = [&](int ch, int tap, int bsel) {
#pragma unroll
        for (int i = 0; i < 8; ++i) {
            int idx = t + i * 128;
            int seg = idx & 7;
            int row = (idx >> 3) & 63;
            int sel = idx >> 9;
            int oc  = n0 + row;
            const __nv_bfloat16* src =
                Bt + (((size_t)tap * OC + oc) * 2 + sel) * IC + ch * 64 + seg * 8;
            cp16(bB + (uint32_t)(bsel * 18432 + sel * 9216 + (row * LDA + seg * 8) * 2),
                 src);
        }
    };

    stageB(0, 0, 0);
    cp_commit();
    int buf = 0;

    for (int ch = 0; ch < NCH; ++ch) {
        __syncthreads();   // all warps done reading sA of previous chunk
        // ---- direct gmem -> bf16 hi/lo transpose: 8 icg x 136 pos ----
        for (int idx = t; idx < 1088; idx += 128) {
            int icg = idx / 136;
            int p   = idx - icg * 136;
            int ry = p / 34, cx = p - ry * 34;
            int y = y0 - 1 + ry;
            int x = cx - 1;
            bool ok = (y >= 0 && y < 32 && x >= 0 && x < 32);
            const float* basep =
                Xg + (((size_t)(img * IC + ch * 64 + icg * 8)) << 10) + (y << 5) + x;
            uint4 vh, vl;
            uint32_t hw[4], lw[4];
#pragma unroll
            for (int pr = 0; pr < 4; ++pr) {
                float v0 = ok ? basep[(size_t)(pr * 2 + 0) << 10] : 0.f;
                float v1 = ok ? basep[(size_t)(pr * 2 + 1) << 10] : 0.f;
                __nv_bfloat16 h0 = __float2bfloat16(v0);
                __nv_bfloat16 h1 = __float2bfloat16(v1);
                __nv_bfloat16 l0 = __float2bfloat16(v0 - __bfloat162float(h0));
                __nv_bfloat16 l1 = __float2bfloat16(v1 - __bfloat162float(h1));
                hw[pr] = (uint32_t)__bfloat16_as_ushort(h0)
                       | ((uint32_t)__bfloat16_as_ushort(h1) << 16);
                lw[pr] = (uint32_t)__bfloat16_as_ushort(l0)
                       | ((uint32_t)__bfloat16_as_ushort(l1) << 16);
            }
            vh.x = hw[0]; vh.y = hw[1]; vh.z = hw[2]; vh.w = hw[3];
            vl.x = lw[0]; vl.y = lw[1]; vl.z = lw[2]; vl.w = lw[3];
            *(uint4*)&sAh[p * LDA + icg * 8] = vh;
            *(uint4*)&sAl[p * LDA + icg * 8] = vl;
        }
        __syncthreads();   // sA ready
        // ---- 9 taps, B double-buffered, one barrier per tap ----
        for (int tap = 0; tap < 9; ++tap) {
            cp_wait_all();
            __syncthreads();
            int g = ch * 9 + tap;
            if (g + 1 < total_taps) {
                int gn = g + 1;
                stageB(gn / 9, gn - (gn / 9) * 9, buf ^ 1);
            }
            cp_commit();
            __nv_bfloat16* sBh = (__nv_bfloat16*)(smem + 39168 + buf * 18432);
            __nv_bfloat16* sBl = sBh + 4608;   // +9216 B
            int dy = tap / 3 - 1, dx = tap - (tap / 3) * 3 - 1;
            int abase = ((1 + dy + wm) * 34 + (1 + dx)) * LDA;
#pragma unroll
            for (int ks = 0; ks < 4; ++ks) {
                int kk = ks * 16;
                wmma::fragment<wmma::matrix_a, 16, 16, 16, __nv_bfloat16, wmma::row_major> ah[2], al[2];
                wmma::fragment<wmma::matrix_b, 16, 16, 16, __nv_bfloat16, wmma::col_major> bh[2], bl[2];
                wmma::load_matrix_sync(ah[0], sAh + abase + 0  * LDA + kk, LDA);
                wmma::load_matrix_sync(ah[1], sAh + abase + 16 * LDA + kk, LDA);
                wmma::load_matrix_sync(al[0], sAl + abase + 0  * LDA + kk, LDA);
                wmma::load_matrix_sync(al[1], sAl + abase + 16 * LDA + kk, LDA);
                wmma::load_matrix_sync(bh[0], sBh + (wn * 32 + 0)  * LDA + kk, LDA);
                wmma::load_matrix_sync(bh[1], sBh + (wn * 32 + 16) * LDA + kk, LDA);
                wmma::load_matrix_sync(bl[0], sBl + (wn * 32 + 0)  * LDA + kk, LDA);
                wmma::load_matrix_sync(bl[1], sBl + (wn * 32 + 16) * LDA + kk, LDA);
#pragma unroll
                for (int i = 0; i < 2; ++i)
#pragma unroll
                    for (int j = 0; j < 2; ++j) {
                        wmma::mma_sync(acc[i][j], ah[i], bh[j], acc[i][j]);
                        wmma::mma_sync(acc[i][j], ah[i], bl[j], acc[i][j]);
                        wmma::mma_sync(acc[i][j], al[i], bh[j], acc[i][j]);
                    }
            }
            buf ^= 1;
        }
    }

    // ---- epilogue: dump accumulators to smem f32 tile [64][68], scatter ----
    __syncthreads();   // all warps done with final LDSM before sD overlays sA
#pragma unroll
    for (int i = 0; i < 2; ++i)
#pragma unroll
        for (int j = 0; j < 2; ++j)
            wmma::store_matrix_sync(sD + (wm * 32 + i * 16) * 68 + wn * 32 + j * 16,
                                    acc[i][j], 68, wmma::mem_row_major);
    __syncthreads();

    int r = t & 63, q = t >> 6;        // 64 rows x 2 col-blocks of 32
    int px = m0 + r;
    const float* drow = sD + r * 68 + q * 32;
    if (EPI == 0) {
        int im = px >> 10, p = px & 1023;
        int bb = im / 3, ss = im - bb * 3;
        float* dst = g_xg + bb * 393216 + ss * 131072 + p;
#pragma unroll
        for (int c = 0; c < 32; ++c) {
            int oc = n0 + q * 32 + c;
            dst[oc * 1024] = drow[c] + bias[oc] + pos[oc * 1024 + p];
        }
    } else {
        int im = px >> 10, p = px & 1023;
        int y = p >> 5, xg = p & 31;
#pragma unroll
        for (int c = 0; c < 32; ++c) {
            int oc = n0 + q * 32 + c;
            int p1 = oc / 56, rr2 = oc - p1 * 56;
            int p2 = rr2 / 7, e = rr2 - p2 * 7;
            g_u[((size_t)(im * 7 + e) * 256 + (size_t)(y * 8 + p1)) * 256
                + (size_t)(xg * 8 + p2)] = drow[c] + bias[oc];
        }
    }
}

// ---------------- K3: GroupNorm stats (64 contiguous groups of 24576) ----------------
__global__ void k_gnstats() {
    int bg = blockIdx.x;
    const float* p = g_xg + bg * 24576;
    int t = threadIdx.x;
    float s = 0.f, s2 = 0.f;
    for (int i = t; i < 24576; i += 256) { float v = p[i]; s += v; s2 += v * v; }
    __shared__ float rs[256], rq[256];
    rs[t] = s; rq[t] = s2; __syncthreads();
    for (int off = 128; off > 0; off >>= 1) {
        if (t < off) { rs[t] += rs[t + off]; rq[t] += rq[t + off]; }
        __syncthreads();
    }
    if (t == 0) {
        float mu = rs[0] * (1.f / 24576.f);
        float var = rq[0] * (1.f / 24576.f) - mu * mu;
        g_gn_mu[bg] = mu;
        g_gn_rs[bg] = rsqrtf(var + EPSV);
    }
}

// ---------------- K4: S-collapse with GN applied ----------------
__global__ void k_xq(const float* __restrict__ gamma, const float* __restrict__ beta,
                     const float* __restrict__ w2) {
    int idx = blockIdx.x * 256 + threadIdx.x;
    if (idx >= 4096 * 128) return;
    int nq = idx >> 7, dq = idx & 127;
    int b = nq >> 10;
    int fbase = (nq & 1023) * 384 + dq * 3;
    const float* xb = g_xg + b * 393216;
    float accv = 0.f;
#pragma unroll
    for (int sq = 0; sq < 3; ++sq) {
        int f  = fbase + sq;
        int dp = f / 3072;
        int gi = b * 16 + f / 24576;
        float v = xb[f];
        float xn = (v - g_gn_mu[gi]) * g_gn_rs[gi] * gamma[dp] + beta[dp];
        accv = fmaf(w2[sq], xn, accv);
    }
    g_xq[idx] = accv;
}

// ---------------- K5: q GEMM (4096x128 @ 128x256) ----------------
__global__ void __launch_bounds__(256) k_qgemm(const float* __restrict__ w1,
                                               const float* __restrict__ b1,
                                               const float* __restrict__ w2,
                                               const float* __restrict__ b2p) {
    __shared__ float As[64 * 68];
    __shared__ float Bs[64 * 68];
    int r0 = blockIdx.x * 64, o0 = blockIdx.y * 64;
    int t = threadIdx.x;
    int cth = (t & 15) * 4, rth = (t >> 4) * 4;
    float acc[4][4];
#pragma unroll
    for (int a = 0; a < 4; ++a)
#pragma unroll
        for (int c = 0; c < 4; ++c) acc[a][c] = 0.f;

    for (int k0 = 0; k0 < 128; k0 += 64) {
        __syncthreads();
        for (int idx = t; idx < 4096; idx += 256) {
            int jj = idx & 63, rr = idx >> 6;
            As[jj * 68 + rr] = g_xq[(r0 + rr) * 128 + k0 + jj];
            Bs[jj * 68 + rr] = w1[(o0 + rr) * 128 + k0 + jj];
        }
        __syncthreads();
#pragma unroll 8
        for (int j = 0; j < 64; ++j) {
            float4 av = *(const float4*)&As[j * 68 + rth];
            float4 bv = *(const float4*)&Bs[j * 68 + cth];
            float a[4] = {av.x, av.y, av.z, av.w};
            float bb[4] = {bv.x, bv.y, bv.z, bv.w};
#pragma unroll
            for (int r = 0; r < 4; ++r)
#pragma unroll
                for (int c = 0; c < 4; ++c) acc[r][c] = fmaf(a[r], bb[c], acc[r][c]);
        }
    }
    float w2s = w2[0] + w2[1] + w2[2];
    float b2v = b2p[0];
#pragma unroll
    for (int r = 0; r < 4; ++r)
#pragma unroll
        for (int c = 0; c < 4; ++c) {
            int o = o0 + cth + c;
            g_q[(r0 + rth + r) * 256 + o] = acc[r][c] + b1[o] * w2s + b2v;
        }
}

// ---------------- K6: per-row attention (16384 rows) ----------------
__global__ void __launch_bounds__(128) k_attn(const float* __restrict__ kc,
                                              const float* __restrict__ vc) {
    int n = blockIdx.x;
    int t = threadIdx.x;
    int lane = t & 31, wid = t >> 5;
    __shared__ float attn_s[128];
    __shared__ float red[128];

    const float* qp = g_q + (size_t)(n >> 2) * 256 + (n & 3) * 64;
    float2 q2 = *(const float2*)(qp + 2 * lane);
    const float* kb = kc + (size_t)n * 8192;

#pragma unroll 4
    for (int i = 0; i < 32; ++i) {
        int l = wid * 32 + i;
        float2 kv = *(const float2*)(kb + l * 64 + 2 * lane);
        float p = q2.x * kv.x + q2.y * kv.y;
        p += __shfl_xor_sync(0xffffffffu, p, 16);
        p += __shfl_xor_sync(0xffffffffu, p, 8);
        p += __shfl_xor_sync(0xffffffffu, p, 4);
        p += __shfl_xor_sync(0xffffffffu, p, 2);
        p += __shfl_xor_sync(0xffffffffu, p, 1);
        if (lane == i) attn_s[l] = p * 0.125f;
    }
    __syncthreads();

    float v = attn_s[t];
    float m = v;
    m = fmaxf(m, __shfl_xor_sync(0xffffffffu, m, 16));
    m = fmaxf(m, __shfl_xor_sync(0xffffffffu, m, 8));
    m = fmaxf(m, __shfl_xor_sync(0xffffffffu, m, 4));
    m = fmaxf(m, __shfl_xor_sync(0xffffffffu, m, 2));
    m = fmaxf(m, __shfl_xor_sync(0xffffffffu, m, 1));
    if (lane == 0) red[wid] = m;
    __syncthreads();
    float bm = fmaxf(fmaxf(red[0], red[1]), fmaxf(red[2], red[3]));
    float e = expf(v - bm);
    float s = e;
    s += __shfl_xor_sync(0xffffffffu, s, 16);
    s += __shfl_xor_sync(0xffffffffu, s, 8);
    s += __shfl_xor_sync(0xffffffffu, s, 4);
    s += __shfl_xor_sync(0xffffffffu, s, 2);
    s += __shfl_xor_sync(0xffffffffu, s, 1);
    __syncthreads();
    if (lane == 0) red[wid] = s;
    __syncthreads();
    float bs = red[0] + red[1] + red[2] + red[3];
    attn_s[t] = e * (1.f / bs);
    __syncthreads();

    int c = t & 31, chunk = t >> 5;
    const float* vb = vc + (size_t)n * 4096;
    float acc = 0.f;
#pragma unroll 8
    for (int i = 0; i < 32; ++i) {
        int l = chunk * 32 + i;
        acc = fmaf(attn_s[l], vb[l * 32 + c], acc);
    }
    __syncthreads();
    red[t] = acc;
    __syncthreads();
    if (t < 32) {
        float o = red[t] + red[32 + t] + red[64 + t] + red[96 + t];
        g_oflat[(n & 4095) * 128 + (n >> 12) * 32 + t] = o;
    }
}

// ---------------- K7: outproj 128x128 per-pixel matvec ----------------
__global__ void __launch_bounds__(256) k_outproj(const float* __restrict__ w,
                                                 const float* __restrict__ bias) {
    __shared__ float in_s[32 * 128];
    __shared__ float w_s[32 * 36];
    int b = blockIdx.x >> 3, pt = blockIdx.x & 7;
    int oc0 = blockIdx.y * 32;
    int t = threadIdx.x;
    int tx = t & 15, ty = t >> 4;
    int p0 = tx * 8, ol = ty * 2;
    float acc[2][8];
#pragma unroll
    for (int j = 0; j < 2; ++j)
#pragma unroll
        for (int i = 0; i < 8; ++i) acc[j][i] = 0.f;

    for (int c0 = 0; c0 < 128; c0 += 32) {
        __syncthreads();
        for (int idx = t; idx < 32 * 128; idx += 256) {
            int c = idx >> 7, p = idx & 127;
            in_s[idx] = g_oflat[b * 131072 + (c0 + c) * 1024 + pt * 128 + p];
        }
        for (int idx = t; idx < 32 * 32; idx += 256) {
            int c = idx & 31, o = idx >> 5;
            w_s[c * 36 + o] = w[(oc0 + o) * 128 + c0 + c];
        }
        __syncthreads();
#pragma unroll 4
        for (int c = 0; c < 32; ++c) {
            float w0 = w_s[c * 36 + ol], w1 = w_s[c * 36 + ol + 1];
            float4 i0 = *(const float4*)&in_s[c * 128 + p0];
            float4 i1 = *(const float4*)&in_s[c * 128 + p0 + 4];
            float iv[8] = {i0.x, i0.y, i0.z, i0.w, i1.x, i1.y, i1.z, i1.w};
#pragma unroll
            for (int i = 0; i < 8; ++i) {
                acc[0][i] = fmaf(w0, iv[i], acc[0][i]);
                acc[1][i] = fmaf(w1, iv[i], acc[1][i]);
            }
        }
    }
#pragma unroll
    for (int j = 0; j < 2; ++j) {
        int oc = oc0 + ol + j;
        float bv = bias[oc];
#pragma unroll
        for (int i = 0; i < 8; ++i)
            g_o2[(b * 128 + oc) * 1024 + pt * 128 + p0 + i] = acc[j][i] + bv;
    }
}

// ---------------- K9: modulation ----------------
__global__ void k_mod(const float* __restrict__ emb, const float* __restrict__ mw,
                      const float* __restrict__ mb) {
    int t = threadIdx.x;
    if (t < 56) {
        int b = t / 14, o = t % 14;
        float accv = mb[o];
        for (int k = 0; k < 256; ++k) {
            float e = emb[b * 256 + k];
            float si = e / (1.f + expf(-e));
            accv = fmaf(si, mw[o * 256 + k], accv);
        }
        g_mod[t] = accv;
    }
}

// ---------------- K10/K11: LayerNorm over u per batch ----------------
__global__ void k_lnpart() {
    int bidx = blockIdx.x;
    int b = bidx >> 5, part = bidx & 31;
    const float* p = g_u + b * 458752 + part * 14336;
    int t = threadIdx.x;
    float s = 0.f, s2 = 0.f;
    for (int i = t; i < 14336; i += 256) { float v = p[i]; s += v; s2 += v * v; }
    __shared__ float rs[256], rq[256];
    rs[t] = s; rq[t] = s2; __syncthreads();
    for (int off = 128; off > 0; off >>= 1) {
        if (t < off) { rs[t] += rs[t + off]; rq[t] += rq[t + off]; }
        __syncthreads();
    }
    if (t == 0) { g_lnp[bidx * 2] = rs[0]; g_lnp[bidx * 2 + 1] = rq[0]; }
}

__global__ void k_lnfin() {
    int t = threadIdx.x;
    if (t < 4) {
        float s = 0.f, s2 = 0.f;
        for (int i = 0; i < 32; ++i) {
            s  += g_lnp[(t * 32 + i) * 2];
            s2 += g_lnp[(t * 32 + i) * 2 + 1];
        }
        float mu = s * (1.f / 458752.f);
        float var = s2 * (1.f / 458752.f) - mu * mu;
        g_ln[t * 2] = mu;
        g_ln[t * 2 + 1] = rsqrtf(var + EPSV);
    }
}

// ---------------- K12: final elementwise tail ----------------
__device__ __forceinline__ float gelu_exact(float x) {
    return 0.5f * x * (1.f + erff(x * 0.70710678118654752f));
}

__global__ void k_final(const float* __restrict__ ew, const float* __restrict__ eb,
                        const float* __restrict__ fw, const float* __restrict__ fb,
                        float* __restrict__ out) {
    int gid = blockIdx.x * 256 + threadIdx.x;
    if (gid >= 262144) return;
    int b = gid >> 16, p = gid & 65535;
    float mu = g_ln[b * 2], rsd = g_ln[b * 2 + 1];
    float uv[7], un[7];
#pragma unroll
    for (int e = 0; e < 7; ++e) {
        uv[e] = g_u[b * 458752 + e * 65536 + p];
        float sc = g_mod[b * 14 + e];
        float sh = g_mod[b * 14 + 7 + e];
        un[e] = (uv[e] - mu) * rsd * (1.f + sc) + sh;
    }
    float en[14];
#pragma unroll
    for (int o = 0; o < 14; ++o) {
        float a = eb[o];
#pragma unroll
        for (int e = 0; e < 7; ++e) a = fmaf(ew[o * 7 + e], un[e], a);
        en[o] = a;
    }
    float hf[7];
#pragma unroll
    for (int e = 0; e < 7; ++e)
        hf[e] = gelu_exact(un[e]) + en[e] * gelu_exact(en[7 + e]);
#pragma unroll
    for (int o = 0; o < 7; ++o) {
        float a = fb[o];
#pragma unroll
        for (int e = 0; e < 7; ++e) a = fmaf(fw[o * 7 + e], hf[e], a);
        out[b * 458752 + o * 65536 + p] = a + uv[o];
    }
}

// ---------------- launch ----------------
extern "C" void kernel_launch(void* const* d_in, const int* in_sizes, int n_in,
                              void* d_out, int out_size) {
    const float* x    = (const float*)d_in[0];
    const float* kc   = (const float*)d_in[1];
    const float* vc   = (const float*)d_in[2];
    const float* emb  = (const float*)d_in[3];
    const float* pos  = (const float*)d_in[4];
    const float* pw   = (const float*)d_in[5];
    const float* pb   = (const float*)d_in[6];
    const float* gg   = (const float*)d_in[7];
    const float* gb   = (const float*)d_in[8];
    const float* w1   = (const float*)d_in[9];
    const float* b1   = (const float*)d_in[10];
    const float* w2   = (const float*)d_in[11];
    const float* b2   = (const float*)d_in[12];
    const float* ow   = (const float*)d_in[13];
    const float* ob   = (const float*)d_in[14];
    const float* uw   = (const float*)d_in[15];
    const float* ub   = (const float*)d_in[16];
    const float* mw   = (const float*)d_in[17];
    const float* mb   = (const float*)d_in[18];
    const float* ew   = (const float*)d_in[19];
    const float* ebb  = (const float*)d_in[20];
    const float* fw   = (const float*)d_in[21];
    const float* fb   = (const float*)d_in[22];
    float* out = (float*)d_out;

    const int DSMEM = 76032;
    cudaFuncSetAttribute(k_conv<448, 0>,
                         cudaFuncAttributeMaxDynamicSharedMemorySize, DSMEM);
    cudaFuncSetAttribute(k_conv<128, 1>,
                         cudaFuncAttributeMaxDynamicSharedMemorySize, DSMEM);

    __nv_bfloat16 *pBt1, *pBt2;
    cudaGetSymbolAddress((void**)&pBt1, g_Bt1);
    cudaGetSymbolAddress((void**)&pBt2, g_Bt2);
    float* pXin; cudaGetSymbolAddress((void**)&pXin, g_xin);
    float* pO2;  cudaGetSymbolAddress((void**)&pO2,  g_o2);

    k_patchify<<<5376, 256>>>(x);
    k_prepT<<<(128 * 448 * 9 + 255) / 256, 256>>>(pw, pBt1, 128, 448);
    k_prepT<<<(448 * 128 * 9 + 255) / 256, 256>>>(uw, pBt2, 448, 128);
    k_conv<448, 0><<<dim3(192, 2), 128, DSMEM>>>(pXin, pBt1, pb, pos);
    k_gnstats<<<64, 256>>>();
    k_xq<<<2048, 256>>>(gg, gb, w2);
    k_qgemm<<<dim3(64, 4), 256>>>(w1, b1, w2, b2);
    k_attn<<<16384, 128>>>(kc, vc);
    k_outproj<<<dim3(32, 4), 256>>>(ow, ob);
    k_conv<128, 1><<<dim3(64, 7), 128, DSMEM>>>(pO2, pBt2, ub, (const float*)0);
    k_mod<<<1, 64>>>(emb, mw, mb);
    k_lnpart<<<128, 256>>>();
    k_lnfin<<<1, 32>>>();
    k_final<<<1024, 256>>>(ew, ebb, fw, fb, out);
}